// round 5
// baseline (speedup 1.0000x reference)
#include <cuda_runtime.h>
#include <cstdint>

// ---------------- problem constants ----------------
static constexpr int B_   = 2;
static constexpr int S_   = 2048;
static constexpr int D_   = 1024;
static constexpr int H_   = 16;
static constexpr int HD_  = 64;
static constexpr int M_   = B_ * S_;    // 4096
static constexpr int BH_  = B_ * H_;    // 32
static constexpr int QT_  = 128;        // attn q-tile rows
static constexpr int NQT2_ = S_ / QT_;  // 16
static constexpr float INV_SCALE = 0.125f;  // 1/sqrt(64)

// ---------------- device scratch ----------------
__device__ __align__(256) float g_q [(size_t)BH_ * S_ * HD_];
__device__ __align__(256) float g_k [(size_t)BH_ * S_ * HD_];
__device__ __align__(256) float g_v [(size_t)BH_ * S_ * HD_];
__device__ __align__(256) float g_ao[(size_t)M_ * D_];

// ---------------- helpers ----------------
__device__ __forceinline__ uint32_t smem_u32(const void* p) {
    uint32_t a;
    asm("{ .reg .u64 t; cvta.to.shared.u64 t, %1; cvt.u32.u64 %0, t; }" : "=r"(a) : "l"(p));
    return a;
}
__device__ __forceinline__ void cp_async16(uint32_t saddr, const void* gaddr) {
    asm volatile("cp.async.cg.shared.global [%0], [%1], 16;" :: "r"(saddr), "l"(gaddr));
}
__device__ __forceinline__ uint32_t f2tf(float f) {
    uint32_t u;
    asm("cvt.rna.tf32.f32 %0, %1;" : "=r"(u) : "f"(f));
    return u;
}
// C += A(16x8 row) * B(8x8 col), tf32
__device__ __forceinline__ void mma8(float* c, uint32_t a0, uint32_t a1, uint32_t a2,
                                     uint32_t a3, uint32_t b0, uint32_t b1) {
    asm volatile(
        "mma.sync.aligned.m16n8k8.row.col.f32.tf32.tf32.f32 "
        "{%0,%1,%2,%3}, {%4,%5,%6,%7}, {%8,%9}, {%0,%1,%2,%3};"
        : "+f"(c[0]), "+f"(c[1]), "+f"(c[2]), "+f"(c[3])
        : "r"(a0), "r"(a1), "r"(a2), "r"(a3), "r"(b0), "r"(b1));
}

// ============================================================
// tf32 mma GEMM: C[M,N] = A[M,K] @ W[N,K]^T + bias[N]
// CTA 128x128, 8 warps (2m x 4n), warp tile 64x32, BK=16,
// 3-stage cp.async pipeline (dynamic smem).
// mode 1/2/3: write g_q/g_k/g_v reshaped; mode 0/4: plain (4: A=g_ao)
// ============================================================
static constexpr int SA_ = 20;
static constexpr int GEMM_SMEM = 3 * 128 * SA_ * 2 * 4;  // 61440 B

__global__ __launch_bounds__(256, 2) void gemm_tc_kernel(
    const float* __restrict__ Ain, const float* __restrict__ W,
    const float* __restrict__ bias, float* __restrict__ outPlain, int mode)
{
    extern __shared__ float smg[];
    float* As = smg;                   // [3][128*SA_]
    float* Bs = smg + 3 * 128 * SA_;

    const float* A = (mode == 4) ? g_ao : Ain;
    const int tid  = threadIdx.x;
    const int lane = tid & 31;
    const int w    = tid >> 5;
    const int gg   = lane >> 2;
    const int t4   = lane & 3;
    const int wm   = w & 1;
    const int wn   = w >> 1;
    const int rowBase = blockIdx.y * 128;
    const int colBase = blockIdx.x * 128;
    const int K = D_;

    const uint32_t sA = smem_u32(As);
    const uint32_t sB = smem_u32(Bs);

    auto stage = [&](int st, int k0) {
#pragma unroll
        for (int ii = 0; ii < 2; ii++) {
            int idx = tid * 2 + ii;       // 0..511
            int row = idx >> 2;           // 0..127
            int c4  = (idx & 3) * 4;      // 0,4,8,12
            uint32_t off = (uint32_t)(st * 128 * SA_ + row * SA_ + c4) * 4u;
            cp_async16(sA + off, &A[(size_t)(rowBase + row) * K + k0 + c4]);
            cp_async16(sB + off, &W[(size_t)(colBase + row) * K + k0 + c4]);
        }
        asm volatile("cp.async.commit_group;" ::: "memory");
    };

    float c[4][4][4];
#pragma unroll
    for (int i = 0; i < 4; i++)
#pragma unroll
        for (int j = 0; j < 4; j++)
#pragma unroll
            for (int q = 0; q < 4; q++) c[i][j][q] = 0.f;

    const int NCH = K / 16;  // 64
    stage(0, 0);
    stage(1, 16);
    stage(2, 32);

    for (int ch = 0; ch < NCH; ch++) {
        const int buf = ch % 3;
        const int rem = NCH - 1 - ch;
        if (rem >= 2)      asm volatile("cp.async.wait_group 2;" ::: "memory");
        else if (rem == 1) asm volatile("cp.async.wait_group 1;" ::: "memory");
        else               asm volatile("cp.async.wait_group 0;" ::: "memory");
        __syncthreads();

        const float* Ab = As + buf * 128 * SA_;
        const float* Bb = Bs + buf * 128 * SA_;
#pragma unroll
        for (int kk = 0; kk < 16; kk += 8) {
            uint32_t af[4][4], bf[4][2];
#pragma unroll
            for (int i = 0; i < 4; i++) {
                int r0 = wm * 64 + i * 16 + gg;
                af[i][0] = f2tf(Ab[r0 * SA_ + kk + t4]);
                af[i][1] = f2tf(Ab[(r0 + 8) * SA_ + kk + t4]);
                af[i][2] = f2tf(Ab[r0 * SA_ + kk + t4 + 4]);
                af[i][3] = f2tf(Ab[(r0 + 8) * SA_ + kk + t4 + 4]);
            }
#pragma unroll
            for (int j = 0; j < 4; j++) {
                int n0 = wn * 32 + j * 8 + gg;
                bf[j][0] = f2tf(Bb[n0 * SA_ + kk + t4]);
                bf[j][1] = f2tf(Bb[n0 * SA_ + kk + t4 + 4]);
            }
#pragma unroll
            for (int i = 0; i < 4; i++)
#pragma unroll
                for (int j = 0; j < 4; j++)
                    mma8(c[i][j], af[i][0], af[i][1], af[i][2], af[i][3],
                         bf[j][0], bf[j][1]);
        }
        __syncthreads();
        if (ch + 3 < NCH) stage(buf, (ch + 3) * 16);
    }

    // epilogue
    float* tgt = (mode == 1) ? g_q : (mode == 2) ? g_k : (mode == 3) ? g_v : outPlain;
#pragma unroll
    for (int i = 0; i < 4; i++) {
#pragma unroll
        for (int j = 0; j < 4; j++) {
            int r0  = rowBase + wm * 64 + i * 16 + gg;
            int col = colBase + wn * 32 + j * 8 + 2 * t4;
            float2 b2 = *(const float2*)&bias[col];
#pragma unroll
            for (int h = 0; h < 2; h++) {
                int m = r0 + h * 8;
                float2 v;
                v.x = c[i][j][h * 2 + 0] + b2.x;
                v.y = c[i][j][h * 2 + 1] + b2.y;
                if (mode == 0 || mode == 4) {
                    *(float2*)&tgt[(size_t)m * D_ + col] = v;
                } else {
                    int bb = m >> 11, ss = m & (S_ - 1);
                    int hh = col >> 6, hd = col & 63;
                    *(float2*)&tgt[(((size_t)(bb * H_ + hh)) * S_ + ss) * HD_ + hd] = v;
                }
            }
        }
    }
}

// ============================================================
// Fused causal attention, two sweeps, per (b,h, 128-row q-tile).
// 256 threads, 8 warps (4m x 2n over 128x64 S tile).
// Sweep 1: S=QK^T, exp, rowsums only.
// Sweep 2: recompute S, e_norm = exp*inv, write P once (normalized),
//          accumulate O = E_norm @ V. Fully-masked tiles: zero-fill P.
// Q/K/V held in smem as pre-converted tf32; E held as fp32.
// ============================================================
static constexpr int SQ_ = 68;   // Qs / KE row stride (floats)
static constexpr int SV_ = 72;   // Vs row stride
static constexpr int ATTN_SMEM = (2 * QT_ * SQ_ + 64 * SV_ + 128) * 4;  // 88576 B

__global__ __launch_bounds__(256, 2) void attn_kernel(float* __restrict__ P, int writeP)
{
    extern __shared__ float sm[];
    float* Qs    = sm;                      // [128][SQ_] tf32 bits
    float* KE    = sm + QT_ * SQ_;          // K tf32 bits (rows 0..63) / E fp32 [128][SQ_]
    float* Vs    = sm + 2 * QT_ * SQ_;      // [64][SV_] tf32 bits (also rowsum scratch)
    float* inv_s = Vs + 64 * SV_;           // [128]

    const int tid  = threadIdx.x;
    const int lane = tid & 31;
    const int w    = tid >> 5;
    const int gg   = lane >> 2;
    const int t4   = lane & 3;
    const int wm   = w & 3;   // 4 slices of 32 rows
    const int wn   = w >> 2;  // 2 slices of 32 cols
    const int qt   = (NQT2_ - 1) - (int)blockIdx.x;
    const int bh   = blockIdx.y;
    const int q0   = qt * QT_;

    const float* Qg = g_q + (size_t)bh * S_ * HD_;
    const float* Kg = g_k + (size_t)bh * S_ * HD_;
    const float* Vg = g_v + (size_t)bh * S_ * HD_;

    // load Q tile once: 128x64, convert to tf32 at stage time
#pragma unroll
    for (int i = 0; i < 8; i++) {
        int idx = tid + i * 256;
        int row = idx >> 4, cc = (idx & 15) * 4;
        float4 qv = *(const float4*)&Qg[(size_t)(q0 + row) * HD_ + cc];
        uint32_t* dst = (uint32_t*)&Qs[row * SQ_ + cc];
        dst[0] = f2tf(qv.x); dst[1] = f2tf(qv.y);
        dst[2] = f2tf(qv.z); dst[3] = f2tf(qv.w);
    }

    const int nkt = 2 * qt + 2;  // causal k-tiles for this 128-row block

    // ================= sweep 1: rowsums =================
    float rs[2][2] = {{0.f, 0.f}, {0.f, 0.f}};
    for (int kt = 0; kt < nkt; kt++) {
        const int k0 = kt * 64;
        __syncthreads();
#pragma unroll
        for (int i = 0; i < 4; i++) {
            int idx = tid + i * 256;
            int row = idx >> 4, cc = (idx & 15) * 4;
            float4 kv = *(const float4*)&Kg[(size_t)(k0 + row) * HD_ + cc];
            uint32_t* dst = (uint32_t*)&KE[row * SQ_ + cc];
            dst[0] = f2tf(kv.x); dst[1] = f2tf(kv.y);
            dst[2] = f2tf(kv.z); dst[3] = f2tf(kv.w);
        }
        __syncthreads();

        float s[2][4][4];
#pragma unroll
        for (int i = 0; i < 2; i++)
#pragma unroll
            for (int j = 0; j < 4; j++)
#pragma unroll
                for (int q = 0; q < 4; q++) s[i][j][q] = 0.f;
#pragma unroll
        for (int kk = 0; kk < 64; kk += 8) {
            uint32_t af[2][4], bf[4][2];
#pragma unroll
            for (int i = 0; i < 2; i++) {
                int r0 = wm * 32 + i * 16 + gg;
                af[i][0] = __float_as_uint(Qs[r0 * SQ_ + kk + t4]);
                af[i][1] = __float_as_uint(Qs[(r0 + 8) * SQ_ + kk + t4]);
                af[i][2] = __float_as_uint(Qs[r0 * SQ_ + kk + t4 + 4]);
                af[i][3] = __float_as_uint(Qs[(r0 + 8) * SQ_ + kk + t4 + 4]);
            }
#pragma unroll
            for (int j = 0; j < 4; j++) {
                int n0 = wn * 32 + j * 8 + gg;
                bf[j][0] = __float_as_uint(KE[n0 * SQ_ + kk + t4]);
                bf[j][1] = __float_as_uint(KE[n0 * SQ_ + kk + t4 + 4]);
            }
#pragma unroll
            for (int i = 0; i < 2; i++)
#pragma unroll
                for (int j = 0; j < 4; j++)
                    mma8(s[i][j], af[i][0], af[i][1], af[i][2], af[i][3],
                         bf[j][0], bf[j][1]);
        }
#pragma unroll
        for (int i = 0; i < 2; i++) {
            int qiA = q0 + wm * 32 + i * 16 + gg, qiB = qiA + 8;
#pragma unroll
            for (int j = 0; j < 4; j++) {
                int ki0 = k0 + wn * 32 + j * 8 + 2 * t4, ki1 = ki0 + 1;
                rs[i][0] += ((ki0 <= qiA) ? __expf(s[i][j][0] * INV_SCALE) : 0.f)
                          + ((ki1 <= qiA) ? __expf(s[i][j][1] * INV_SCALE) : 0.f);
                rs[i][1] += ((ki0 <= qiB) ? __expf(s[i][j][2] * INV_SCALE) : 0.f)
                          + ((ki1 <= qiB) ? __expf(s[i][j][3] * INV_SCALE) : 0.f);
            }
        }
    }
    // reduce rowsums: lanes t4 0..3, then the 2 wn warps via smem (Vs scratch)
#pragma unroll
    for (int i = 0; i < 2; i++) {
#pragma unroll
        for (int h = 0; h < 2; h++) {
            rs[i][h] += __shfl_xor_sync(0xFFFFFFFF, rs[i][h], 1);
            rs[i][h] += __shfl_xor_sync(0xFFFFFFFF, rs[i][h], 2);
        }
    }
    __syncthreads();
    if (t4 == 0) {
#pragma unroll
        for (int i = 0; i < 2; i++) {
            int r0 = wm * 32 + i * 16 + gg;
            Vs[wn * 128 + r0]     = rs[i][0];
            Vs[wn * 128 + r0 + 8] = rs[i][1];
        }
    }
    __syncthreads();
    if (tid < 128) inv_s[tid] = 1.f / (Vs[tid] + Vs[128 + tid]);
    __syncthreads();

    // ================= sweep 2: P + O =================
    float o[2][4][4];
#pragma unroll
    for (int i = 0; i < 2; i++)
#pragma unroll
        for (int j = 0; j < 4; j++)
#pragma unroll
            for (int q = 0; q < 4; q++) o[i][j][q] = 0.f;

    for (int kt = 0; kt < S_ / 64; kt++) {
        const int k0 = kt * 64;
        if (kt < nkt) {
            __syncthreads();
#pragma unroll
            for (int i = 0; i < 4; i++) {
                int idx = tid + i * 256;
                int row = idx >> 4, cc = (idx & 15) * 4;
                float4 kv = *(const float4*)&Kg[(size_t)(k0 + row) * HD_ + cc];
                uint32_t* dk = (uint32_t*)&KE[row * SQ_ + cc];
                dk[0] = f2tf(kv.x); dk[1] = f2tf(kv.y);
                dk[2] = f2tf(kv.z); dk[3] = f2tf(kv.w);
                float4 vv = *(const float4*)&Vg[(size_t)(k0 + row) * HD_ + cc];
                uint32_t* dv = (uint32_t*)&Vs[row * SV_ + cc];
                dv[0] = f2tf(vv.x); dv[1] = f2tf(vv.y);
                dv[2] = f2tf(vv.z); dv[3] = f2tf(vv.w);
            }
            __syncthreads();

            float s[2][4][4];
#pragma unroll
            for (int i = 0; i < 2; i++)
#pragma unroll
                for (int j = 0; j < 4; j++)
#pragma unroll
                    for (int q = 0; q < 4; q++) s[i][j][q] = 0.f;
#pragma unroll
            for (int kk = 0; kk < 64; kk += 8) {
                uint32_t af[2][4], bf[4][2];
#pragma unroll
                for (int i = 0; i < 2; i++) {
                    int r0 = wm * 32 + i * 16 + gg;
                    af[i][0] = __float_as_uint(Qs[r0 * SQ_ + kk + t4]);
                    af[i][1] = __float_as_uint(Qs[(r0 + 8) * SQ_ + kk + t4]);
                    af[i][2] = __float_as_uint(Qs[r0 * SQ_ + kk + t4 + 4]);
                    af[i][3] = __float_as_uint(Qs[(r0 + 8) * SQ_ + kk + t4 + 4]);
                }
#pragma unroll
                for (int j = 0; j < 4; j++) {
                    int n0 = wn * 32 + j * 8 + gg;
                    bf[j][0] = __float_as_uint(KE[n0 * SQ_ + kk + t4]);
                    bf[j][1] = __float_as_uint(KE[n0 * SQ_ + kk + t4 + 4]);
                }
#pragma unroll
                for (int i = 0; i < 2; i++)
#pragma unroll
                    for (int j = 0; j < 4; j++)
                        mma8(s[i][j], af[i][0], af[i][1], af[i][2], af[i][3],
                             bf[j][0], bf[j][1]);
            }

            // e_norm = exp * inv (normalized), masked
#pragma unroll
            for (int i = 0; i < 2; i++) {
                int r0 = wm * 32 + i * 16 + gg;
                int qiA = q0 + r0, qiB = qiA + 8;
                float invA = inv_s[r0], invB = inv_s[r0 + 8];
#pragma unroll
                for (int j = 0; j < 4; j++) {
                    int ki0 = k0 + wn * 32 + j * 8 + 2 * t4, ki1 = ki0 + 1;
                    s[i][j][0] = (ki0 <= qiA) ? __expf(s[i][j][0] * INV_SCALE) * invA : 0.f;
                    s[i][j][1] = (ki1 <= qiA) ? __expf(s[i][j][1] * INV_SCALE) * invA : 0.f;
                    s[i][j][2] = (ki0 <= qiB) ? __expf(s[i][j][2] * INV_SCALE) * invB : 0.f;
                    s[i][j][3] = (ki1 <= qiB) ? __expf(s[i][j][3] * INV_SCALE) * invB : 0.f;
                }
            }
            __syncthreads();  // all warps done reading KE as K

            // store E (fp32) into KE
#pragma unroll
            for (int i = 0; i < 2; i++) {
                int r0 = wm * 32 + i * 16 + gg;
#pragma unroll
                for (int j = 0; j < 4; j++) {
                    int cl = wn * 32 + j * 8 + 2 * t4;
                    *(float2*)&KE[r0 * SQ_ + cl]       = make_float2(s[i][j][0], s[i][j][1]);
                    *(float2*)&KE[(r0 + 8) * SQ_ + cl] = make_float2(s[i][j][2], s[i][j][3]);
                }
            }
            __syncthreads();

            // coalesced write of NORMALIZED P
            if (writeP) {
                float* Pd = P + (size_t)bh * S_ * S_ + (size_t)q0 * S_ + k0;
#pragma unroll
                for (int i = 0; i < 8; i++) {
                    int idx = tid + i * 256;
                    int row = idx >> 4, cc = (idx & 15) * 4;
                    *(float4*)&Pd[(size_t)row * S_ + cc] =
                        *(const float4*)&KE[row * SQ_ + cc];
                }
            }

            // O += E_norm @ V
#pragma unroll
            for (int kk = 0; kk < 64; kk += 8) {
                uint32_t af[2][4], bf[4][2];
#pragma unroll
                for (int i = 0; i < 2; i++) {
                    int r0 = wm * 32 + i * 16 + gg;
                    af[i][0] = f2tf(KE[r0 * SQ_ + kk + t4]);
                    af[i][1] = f2tf(KE[(r0 + 8) * SQ_ + kk + t4]);
                    af[i][2] = f2tf(KE[r0 * SQ_ + kk + t4 + 4]);
                    af[i][3] = f2tf(KE[(r0 + 8) * SQ_ + kk + t4 + 4]);
                }
#pragma unroll
                for (int j = 0; j < 4; j++) {
                    int n0 = wn * 32 + j * 8 + gg;
                    bf[j][0] = __float_as_uint(Vs[(kk + t4) * SV_ + n0]);
                    bf[j][1] = __float_as_uint(Vs[(kk + t4 + 4) * SV_ + n0]);
                }
#pragma unroll
                for (int i = 0; i < 2; i++)
#pragma unroll
                    for (int j = 0; j < 4; j++)
                        mma8(o[i][j], af[i][0], af[i][1], af[i][2], af[i][3],
                             bf[j][0], bf[j][1]);
            }
        } else if (writeP) {
            // fully-masked tile: zero-fill P (d_out is poisoned)
            float* Pd = P + (size_t)bh * S_ * S_ + (size_t)q0 * S_ + k0;
            const float4 z = make_float4(0.f, 0.f, 0.f, 0.f);
#pragma unroll
            for (int i = 0; i < 8; i++) {
                int idx = tid + i * 256;
                int row = idx >> 4, cc = (idx & 15) * 4;
                *(float4*)&Pd[(size_t)row * S_ + cc] = z;
            }
        }
    }

    // epilogue: O already normalized
    const int bb = bh >> 4, hh = bh & 15;
#pragma unroll
    for (int i = 0; i < 2; i++) {
        int r0 = wm * 32 + i * 16 + gg;
        int mA = bb * S_ + q0 + r0;
#pragma unroll
        for (int j = 0; j < 4; j++) {
            int cl = hh * 64 + wn * 32 + j * 8 + 2 * t4;
            *(float2*)&g_ao[(size_t)mA * D_ + cl] =
                make_float2(o[i][j][0], o[i][j][1]);
            *(float2*)&g_ao[(size_t)(mA + 8) * D_ + cl] =
                make_float2(o[i][j][2], o[i][j][3]);
        }
    }
}

// ============================================================
extern "C" void kernel_launch(void* const* d_in, const int* in_sizes, int n_in,
                              void* d_out, int out_size)
{
    const float* query = (const float*)d_in[0];
    const float* key_  = (const float*)d_in[1];
    const float* value = (const float*)d_in[2];
    // d_in[3] = causal mask — handled analytically
    const float* Wq = (const float*)d_in[4];
    const float* bq = (const float*)d_in[5];
    const float* Wk = (const float*)d_in[6];
    const float* bk = (const float*)d_in[7];
    const float* Wv = (const float*)d_in[8];
    const float* bv = (const float*)d_in[9];
    const float* Wo = (const float*)d_in[10];
    const float* bo = (const float*)d_in[11];
    float* out = (float*)d_out;

    const long long outN  = (long long)M_ * D_;
    const long long attnN = (long long)BH_ * S_ * S_;

    int hasOut = 1, hasAttn = 0;
    float* Pdst = nullptr;
    if ((long long)out_size >= outN + attnN) { hasAttn = 1; Pdst = out + outN; }
    else if ((long long)out_size == attnN)   { hasOut = 0; hasAttn = 1; Pdst = out; }

    cudaFuncSetAttribute(attn_kernel,
                         cudaFuncAttributeMaxDynamicSharedMemorySize, ATTN_SMEM);
    cudaFuncSetAttribute(gemm_tc_kernel,
                         cudaFuncAttributeMaxDynamicSharedMemorySize, GEMM_SMEM);

    dim3 gg(D_ / 128, M_ / 128);  // (8, 32)
    gemm_tc_kernel<<<gg, 256, GEMM_SMEM>>>(query, Wq, bq, nullptr, 1);
    gemm_tc_kernel<<<gg, 256, GEMM_SMEM>>>(key_,  Wk, bk, nullptr, 2);
    gemm_tc_kernel<<<gg, 256, GEMM_SMEM>>>(value, Wv, bv, nullptr, 3);

    attn_kernel<<<dim3(NQT2_, BH_), 256, ATTN_SMEM>>>(Pdst, hasAttn);

    if (hasOut) gemm_tc_kernel<<<gg, 256, GEMM_SMEM>>>(nullptr, Wo, bo, out, 4);
}

// round 6
// speedup vs baseline: 1.0152x; 1.0152x over previous
#include <cuda_runtime.h>
#include <cstdint>

// ---------------- problem constants ----------------
static constexpr int B_   = 2;
static constexpr int S_   = 2048;
static constexpr int D_   = 1024;
static constexpr int H_   = 16;
static constexpr int HD_  = 64;
static constexpr int M_   = B_ * S_;    // 4096
static constexpr int BH_  = B_ * H_;    // 32
static constexpr int QT_  = 128;        // attn q-tile rows
static constexpr int NQT2_ = S_ / QT_;  // 16
static constexpr float INV_SCALE = 0.125f;  // 1/sqrt(64), exact power of 2

// ---------------- device scratch ----------------
__device__ __align__(256) float g_q [(size_t)BH_ * S_ * HD_];
__device__ __align__(256) float g_k [(size_t)BH_ * S_ * HD_];
__device__ __align__(256) float g_v [(size_t)BH_ * S_ * HD_];
__device__ __align__(256) float g_ao[(size_t)M_ * D_];

// ---------------- helpers ----------------
__device__ __forceinline__ uint32_t smem_u32(const void* p) {
    uint32_t a;
    asm("{ .reg .u64 t; cvta.to.shared.u64 t, %1; cvt.u32.u64 %0, t; }" : "=r"(a) : "l"(p));
    return a;
}
__device__ __forceinline__ void cp_async16(uint32_t saddr, const void* gaddr) {
    asm volatile("cp.async.cg.shared.global [%0], [%1], 16;" :: "r"(saddr), "l"(gaddr));
}
__device__ __forceinline__ uint32_t f2tf(float f) {
    uint32_t u;
    asm("cvt.rna.tf32.f32 %0, %1;" : "=r"(u) : "f"(f));
    return u;
}
// C += A(16x8 row) * B(8x8 col), tf32
__device__ __forceinline__ void mma8(float* c, uint32_t a0, uint32_t a1, uint32_t a2,
                                     uint32_t a3, uint32_t b0, uint32_t b1) {
    asm volatile(
        "mma.sync.aligned.m16n8k8.row.col.f32.tf32.tf32.f32 "
        "{%0,%1,%2,%3}, {%4,%5,%6,%7}, {%8,%9}, {%0,%1,%2,%3};"
        : "+f"(c[0]), "+f"(c[1]), "+f"(c[2]), "+f"(c[3])
        : "r"(a0), "r"(a1), "r"(a2), "r"(a3), "r"(b0), "r"(b1));
}

// ============================================================
// tf32 mma GEMM (R4 version): C[M,N] = A[M,K] @ W[N,K]^T + bias[N]
// CTA 128x128, 8 warps (2m x 4n), warp tile 64x32, BK=16,
// cp.async double buffer, static smem.
// ============================================================
static constexpr int SA_ = 20;

__global__ __launch_bounds__(256, 2) void gemm_tc_kernel(
    const float* __restrict__ Ain, const float* __restrict__ W,
    const float* __restrict__ bias, float* __restrict__ outPlain, int mode)
{
    __shared__ float As[2][128 * SA_];
    __shared__ float Bs[2][128 * SA_];

    const float* A = (mode == 4) ? g_ao : Ain;
    const int tid  = threadIdx.x;
    const int lane = tid & 31;
    const int w    = tid >> 5;
    const int gg   = lane >> 2;
    const int t4   = lane & 3;
    const int wm   = w & 1;
    const int wn   = w >> 1;
    const int rowBase = blockIdx.y * 128;
    const int colBase = blockIdx.x * 128;
    const int K = D_;

    const uint32_t sA = smem_u32(As);
    const uint32_t sB = smem_u32(Bs);

    auto stage = [&](int buf, int k0) {
#pragma unroll
        for (int ii = 0; ii < 2; ii++) {
            int idx = tid * 2 + ii;
            int row = idx >> 2;
            int c4  = (idx & 3) * 4;
            uint32_t off = (uint32_t)(buf * 128 * SA_ + row * SA_ + c4) * 4u;
            cp_async16(sA + off, &A[(size_t)(rowBase + row) * K + k0 + c4]);
            cp_async16(sB + off, &W[(size_t)(colBase + row) * K + k0 + c4]);
        }
        asm volatile("cp.async.commit_group;" ::: "memory");
    };

    float c[4][4][4];
#pragma unroll
    for (int i = 0; i < 4; i++)
#pragma unroll
        for (int j = 0; j < 4; j++)
#pragma unroll
            for (int q = 0; q < 4; q++) c[i][j][q] = 0.f;

    stage(0, 0);
    stage(1, 16);

    const int NCH = K / 16;  // 64
    for (int ch = 0; ch < NCH; ch++) {
        const int buf = ch & 1;
        if (ch < NCH - 1) asm volatile("cp.async.wait_group 1;" ::: "memory");
        else              asm volatile("cp.async.wait_group 0;" ::: "memory");
        __syncthreads();

        const float* Ab = As[buf];
        const float* Bb = Bs[buf];
#pragma unroll
        for (int kk = 0; kk < 16; kk += 8) {
            uint32_t af[4][4], bf[4][2];
#pragma unroll
            for (int i = 0; i < 4; i++) {
                int r0 = wm * 64 + i * 16 + gg;
                af[i][0] = f2tf(Ab[r0 * SA_ + kk + t4]);
                af[i][1] = f2tf(Ab[(r0 + 8) * SA_ + kk + t4]);
                af[i][2] = f2tf(Ab[r0 * SA_ + kk + t4 + 4]);
                af[i][3] = f2tf(Ab[(r0 + 8) * SA_ + kk + t4 + 4]);
            }
#pragma unroll
            for (int j = 0; j < 4; j++) {
                int n0 = wn * 32 + j * 8 + gg;
                bf[j][0] = f2tf(Bb[n0 * SA_ + kk + t4]);
                bf[j][1] = f2tf(Bb[n0 * SA_ + kk + t4 + 4]);
            }
#pragma unroll
            for (int i = 0; i < 4; i++)
#pragma unroll
                for (int j = 0; j < 4; j++)
                    mma8(c[i][j], af[i][0], af[i][1], af[i][2], af[i][3],
                         bf[j][0], bf[j][1]);
        }
        __syncthreads();
        if (ch + 2 < NCH) stage(buf, (ch + 2) * 16);
    }

    float* tgt = (mode == 1) ? g_q : (mode == 2) ? g_k : (mode == 3) ? g_v : outPlain;
#pragma unroll
    for (int i = 0; i < 4; i++) {
#pragma unroll
        for (int j = 0; j < 4; j++) {
            int r0  = rowBase + wm * 64 + i * 16 + gg;
            int col = colBase + wn * 32 + j * 8 + 2 * t4;
            float2 b2 = *(const float2*)&bias[col];
#pragma unroll
            for (int h = 0; h < 2; h++) {
                int m = r0 + h * 8;
                float2 v;
                v.x = c[i][j][h * 2 + 0] + b2.x;
                v.y = c[i][j][h * 2 + 1] + b2.y;
                if (mode == 0 || mode == 4) {
                    *(float2*)&tgt[(size_t)m * D_ + col] = v;
                } else {
                    int bb = m >> 11, ss = m & (S_ - 1);
                    int hh = col >> 6, hd = col & 63;
                    *(float2*)&tgt[(((size_t)(bb * H_ + hh)) * S_ + ss) * HD_ + hd] = v;
                }
            }
        }
    }
}

// ============================================================
// Fused causal attention, two sweeps, per (b,h, 128-row q-tile).
// 256 threads, 8 warps (4m x 2n over 128x64 S tile).
// Q staged pre-scaled (x 1/8, exact) + tf32-converted.
// Sweep 1: Q frags held in REGISTERS (8 LDS + 8 MMA per kk) -> rowsums.
// Sweep 2: recompute S, e_norm = exp*inv, write P once, O += E @ V.
// Mask predication only on diagonal-straddling tiles.
// ============================================================
static constexpr int SQ_ = 68;
static constexpr int SV_ = 72;
static constexpr int ATTN_SMEM = (2 * QT_ * SQ_ + 64 * SV_ + 128) * 4;  // 88576 B

__global__ __launch_bounds__(256, 2) void attn_kernel(float* __restrict__ P, int writeP)
{
    extern __shared__ float sm[];
    float* Qs    = sm;                      // [128][SQ_] tf32 bits, pre-scaled
    float* KE    = sm + QT_ * SQ_;          // K tf32 bits (rows 0..63) / E fp32
    float* Vs    = sm + 2 * QT_ * SQ_;      // [64][SV_] tf32 bits (+ rowsum scratch)
    float* inv_s = Vs + 64 * SV_;           // [128]

    const int tid  = threadIdx.x;
    const int lane = tid & 31;
    const int w    = tid >> 5;
    const int gg   = lane >> 2;
    const int t4   = lane & 3;
    const int wm   = w & 3;
    const int wn   = w >> 2;
    const int qt   = (NQT2_ - 1) - (int)blockIdx.x;
    const int bh   = blockIdx.y;
    const int q0   = qt * QT_;

    const float* Qg = g_q + (size_t)bh * S_ * HD_;
    const float* Kg = g_k + (size_t)bh * S_ * HD_;
    const float* Vg = g_v + (size_t)bh * S_ * HD_;

    // load Q tile once: 128x64, pre-scale by 1/8 (exact) + tf32 convert
#pragma unroll
    for (int i = 0; i < 8; i++) {
        int idx = tid + i * 256;
        int row = idx >> 4, cc = (idx & 15) * 4;
        float4 qv = *(const float4*)&Qg[(size_t)(q0 + row) * HD_ + cc];
        uint32_t* dst = (uint32_t*)&Qs[row * SQ_ + cc];
        dst[0] = f2tf(qv.x * INV_SCALE); dst[1] = f2tf(qv.y * INV_SCALE);
        dst[2] = f2tf(qv.z * INV_SCALE); dst[3] = f2tf(qv.w * INV_SCALE);
    }
    __syncthreads();

    // Q fragments -> registers (invariant across k-tiles)
    uint32_t qf[8][8];
#pragma unroll
    for (int kk = 0; kk < 8; kk++) {
#pragma unroll
        for (int i = 0; i < 2; i++) {
            int r0 = wm * 32 + i * 16 + gg;
            qf[kk][i * 4 + 0] = __float_as_uint(Qs[r0 * SQ_ + kk * 8 + t4]);
            qf[kk][i * 4 + 1] = __float_as_uint(Qs[(r0 + 8) * SQ_ + kk * 8 + t4]);
            qf[kk][i * 4 + 2] = __float_as_uint(Qs[r0 * SQ_ + kk * 8 + t4 + 4]);
            qf[kk][i * 4 + 3] = __float_as_uint(Qs[(r0 + 8) * SQ_ + kk * 8 + t4 + 4]);
        }
    }

    const int nkt = 2 * qt + 2;

    // ================= sweep 1: rowsums =================
    float rs[2][2] = {{0.f, 0.f}, {0.f, 0.f}};
    for (int kt = 0; kt < nkt; kt++) {
        const int k0 = kt * 64;
        __syncthreads();
#pragma unroll
        for (int i = 0; i < 4; i++) {
            int idx = tid + i * 256;
            int row = idx >> 4, cc = (idx & 15) * 4;
            float4 kv = *(const float4*)&Kg[(size_t)(k0 + row) * HD_ + cc];
            uint32_t* dst = (uint32_t*)&KE[row * SQ_ + cc];
            dst[0] = f2tf(kv.x); dst[1] = f2tf(kv.y);
            dst[2] = f2tf(kv.z); dst[3] = f2tf(kv.w);
        }
        __syncthreads();

        float s[2][4][4];
#pragma unroll
        for (int i = 0; i < 2; i++)
#pragma unroll
            for (int j = 0; j < 4; j++)
#pragma unroll
                for (int q = 0; q < 4; q++) s[i][j][q] = 0.f;
#pragma unroll
        for (int kk = 0; kk < 8; kk++) {
            uint32_t bf[4][2];
#pragma unroll
            for (int j = 0; j < 4; j++) {
                int n0 = wn * 32 + j * 8 + gg;
                bf[j][0] = __float_as_uint(KE[n0 * SQ_ + kk * 8 + t4]);
                bf[j][1] = __float_as_uint(KE[n0 * SQ_ + kk * 8 + t4 + 4]);
            }
#pragma unroll
            for (int i = 0; i < 2; i++)
#pragma unroll
                for (int j = 0; j < 4; j++)
                    mma8(s[i][j], qf[kk][i * 4 + 0], qf[kk][i * 4 + 1],
                         qf[kk][i * 4 + 2], qf[kk][i * 4 + 3], bf[j][0], bf[j][1]);
        }

        if (k0 + 63 <= q0 + wm * 32) {
            // fully active for this warp: no masking
#pragma unroll
            for (int i = 0; i < 2; i++)
#pragma unroll
                for (int j = 0; j < 4; j++) {
                    rs[i][0] += __expf(s[i][j][0]) + __expf(s[i][j][1]);
                    rs[i][1] += __expf(s[i][j][2]) + __expf(s[i][j][3]);
                }
        } else {
#pragma unroll
            for (int i = 0; i < 2; i++) {
                int qiA = q0 + wm * 32 + i * 16 + gg, qiB = qiA + 8;
#pragma unroll
                for (int j = 0; j < 4; j++) {
                    int ki0 = k0 + wn * 32 + j * 8 + 2 * t4, ki1 = ki0 + 1;
                    rs[i][0] += ((ki0 <= qiA) ? __expf(s[i][j][0]) : 0.f)
                              + ((ki1 <= qiA) ? __expf(s[i][j][1]) : 0.f);
                    rs[i][1] += ((ki0 <= qiB) ? __expf(s[i][j][2]) : 0.f)
                              + ((ki1 <= qiB) ? __expf(s[i][j][3]) : 0.f);
                }
            }
        }
    }
    // reduce rowsums
#pragma unroll
    for (int i = 0; i < 2; i++) {
#pragma unroll
        for (int h = 0; h < 2; h++) {
            rs[i][h] += __shfl_xor_sync(0xFFFFFFFF, rs[i][h], 1);
            rs[i][h] += __shfl_xor_sync(0xFFFFFFFF, rs[i][h], 2);
        }
    }
    __syncthreads();
    if (t4 == 0) {
#pragma unroll
        for (int i = 0; i < 2; i++) {
            int r0 = wm * 32 + i * 16 + gg;
            Vs[wn * 128 + r0]     = rs[i][0];
            Vs[wn * 128 + r0 + 8] = rs[i][1];
        }
    }
    __syncthreads();
    if (tid < 128) inv_s[tid] = 1.f / (Vs[tid] + Vs[128 + tid]);
    __syncthreads();

    // ================= sweep 2: P + O =================
    float o[2][4][4];
#pragma unroll
    for (int i = 0; i < 2; i++)
#pragma unroll
        for (int j = 0; j < 4; j++)
#pragma unroll
            for (int q = 0; q < 4; q++) o[i][j][q] = 0.f;

    for (int kt = 0; kt < S_ / 64; kt++) {
        const int k0 = kt * 64;
        if (kt < nkt) {
            __syncthreads();
#pragma unroll
            for (int i = 0; i < 4; i++) {
                int idx = tid + i * 256;
                int row = idx >> 4, cc = (idx & 15) * 4;
                float4 kv = *(const float4*)&Kg[(size_t)(k0 + row) * HD_ + cc];
                uint32_t* dk = (uint32_t*)&KE[row * SQ_ + cc];
                dk[0] = f2tf(kv.x); dk[1] = f2tf(kv.y);
                dk[2] = f2tf(kv.z); dk[3] = f2tf(kv.w);
                float4 vv = *(const float4*)&Vg[(size_t)(k0 + row) * HD_ + cc];
                uint32_t* dv = (uint32_t*)&Vs[row * SV_ + cc];
                dv[0] = f2tf(vv.x); dv[1] = f2tf(vv.y);
                dv[2] = f2tf(vv.z); dv[3] = f2tf(vv.w);
            }
            __syncthreads();

            float s[2][4][4];
#pragma unroll
            for (int i = 0; i < 2; i++)
#pragma unroll
                for (int j = 0; j < 4; j++)
#pragma unroll
                    for (int q = 0; q < 4; q++) s[i][j][q] = 0.f;
#pragma unroll
            for (int kk = 0; kk < 8; kk++) {
                uint32_t bf[4][2];
#pragma unroll
                for (int j = 0; j < 4; j++) {
                    int n0 = wn * 32 + j * 8 + gg;
                    bf[j][0] = __float_as_uint(KE[n0 * SQ_ + kk * 8 + t4]);
                    bf[j][1] = __float_as_uint(KE[n0 * SQ_ + kk * 8 + t4 + 4]);
                }
#pragma unroll
                for (int i = 0; i < 2; i++)
#pragma unroll
                    for (int j = 0; j < 4; j++)
                        mma8(s[i][j], qf[kk][i * 4 + 0], qf[kk][i * 4 + 1],
                             qf[kk][i * 4 + 2], qf[kk][i * 4 + 3], bf[j][0], bf[j][1]);
            }

            // e_norm = exp * inv (normalized), masked only on edge tiles
#pragma unroll
            for (int i = 0; i < 2; i++) {
                int r0 = wm * 32 + i * 16 + gg;
                float invA = inv_s[r0], invB = inv_s[r0 + 8];
                if (k0 + 63 <= q0 + wm * 32) {
#pragma unroll
                    for (int j = 0; j < 4; j++) {
                        s[i][j][0] = __expf(s[i][j][0]) * invA;
                        s[i][j][1] = __expf(s[i][j][1]) * invA;
                        s[i][j][2] = __expf(s[i][j][2]) * invB;
                        s[i][j][3] = __expf(s[i][j][3]) * invB;
                    }
                } else {
                    int qiA = q0 + r0, qiB = qiA + 8;
#pragma unroll
                    for (int j = 0; j < 4; j++) {
                        int ki0 = k0 + wn * 32 + j * 8 + 2 * t4, ki1 = ki0 + 1;
                        s[i][j][0] = (ki0 <= qiA) ? __expf(s[i][j][0]) * invA : 0.f;
                        s[i][j][1] = (ki1 <= qiA) ? __expf(s[i][j][1]) * invA : 0.f;
                        s[i][j][2] = (ki0 <= qiB) ? __expf(s[i][j][2]) * invB : 0.f;
                        s[i][j][3] = (ki1 <= qiB) ? __expf(s[i][j][3]) * invB : 0.f;
                    }
                }
            }
            __syncthreads();

            // store E (fp32) into KE
#pragma unroll
            for (int i = 0; i < 2; i++) {
                int r0 = wm * 32 + i * 16 + gg;
#pragma unroll
                for (int j = 0; j < 4; j++) {
                    int cl = wn * 32 + j * 8 + 2 * t4;
                    *(float2*)&KE[r0 * SQ_ + cl]       = make_float2(s[i][j][0], s[i][j][1]);
                    *(float2*)&KE[(r0 + 8) * SQ_ + cl] = make_float2(s[i][j][2], s[i][j][3]);
                }
            }
            __syncthreads();

            // coalesced write of NORMALIZED P
            if (writeP) {
                float* Pd = P + (size_t)bh * S_ * S_ + (size_t)q0 * S_ + k0;
#pragma unroll
                for (int i = 0; i < 8; i++) {
                    int idx = tid + i * 256;
                    int row = idx >> 4, cc = (idx & 15) * 4;
                    *(float4*)&Pd[(size_t)row * S_ + cc] =
                        *(const float4*)&KE[row * SQ_ + cc];
                }
            }

            // O += E_norm @ V
#pragma unroll
            for (int kk = 0; kk < 8; kk++) {
                uint32_t af[2][4], bf[4][2];
#pragma unroll
                for (int i = 0; i < 2; i++) {
                    int r0 = wm * 32 + i * 16 + gg;
                    af[i][0] = f2tf(KE[r0 * SQ_ + kk * 8 + t4]);
                    af[i][1] = f2tf(KE[(r0 + 8) * SQ_ + kk * 8 + t4]);
                    af[i][2] = f2tf(KE[r0 * SQ_ + kk * 8 + t4 + 4]);
                    af[i][3] = f2tf(KE[(r0 + 8) * SQ_ + kk * 8 + t4 + 4]);
                }
#pragma unroll
                for (int j = 0; j < 4; j++) {
                    int n0 = wn * 32 + j * 8 + gg;
                    bf[j][0] = __float_as_uint(Vs[(kk * 8 + t4) * SV_ + n0]);
                    bf[j][1] = __float_as_uint(Vs[(kk * 8 + t4 + 4) * SV_ + n0]);
                }
#pragma unroll
                for (int i = 0; i < 2; i++)
#pragma unroll
                    for (int j = 0; j < 4; j++)
                        mma8(o[i][j], af[i][0], af[i][1], af[i][2], af[i][3],
                             bf[j][0], bf[j][1]);
            }
        } else if (writeP) {
            // fully-masked tile: zero-fill P
            float* Pd = P + (size_t)bh * S_ * S_ + (size_t)q0 * S_ + k0;
            const float4 z = make_float4(0.f, 0.f, 0.f, 0.f);
#pragma unroll
            for (int i = 0; i < 8; i++) {
                int idx = tid + i * 256;
                int row = idx >> 4, cc = (idx & 15) * 4;
                *(float4*)&Pd[(size_t)row * S_ + cc] = z;
            }
        }
    }

    // epilogue: O already normalized
    const int bb = bh >> 4, hh = bh & 15;
#pragma unroll
    for (int i = 0; i < 2; i++) {
        int r0 = wm * 32 + i * 16 + gg;
        int mA = bb * S_ + q0 + r0;
#pragma unroll
        for (int j = 0; j < 4; j++) {
            int cl = hh * 64 + wn * 32 + j * 8 + 2 * t4;
            *(float2*)&g_ao[(size_t)mA * D_ + cl] =
                make_float2(o[i][j][0], o[i][j][1]);
            *(float2*)&g_ao[(size_t)(mA + 8) * D_ + cl] =
                make_float2(o[i][j][2], o[i][j][3]);
        }
    }
}

// ============================================================
extern "C" void kernel_launch(void* const* d_in, const int* in_sizes, int n_in,
                              void* d_out, int out_size)
{
    const float* query = (const float*)d_in[0];
    const float* key_  = (const float*)d_in[1];
    const float* value = (const float*)d_in[2];
    // d_in[3] = causal mask — handled analytically
    const float* Wq = (const float*)d_in[4];
    const float* bq = (const float*)d_in[5];
    const float* Wk = (const float*)d_in[6];
    const float* bk = (const float*)d_in[7];
    const float* Wv = (const float*)d_in[8];
    const float* bv = (const float*)d_in[9];
    const float* Wo = (const float*)d_in[10];
    const float* bo = (const float*)d_in[11];
    float* out = (float*)d_out;

    const long long outN  = (long long)M_ * D_;
    const long long attnN = (long long)BH_ * S_ * S_;

    int hasOut = 1, hasAttn = 0;
    float* Pdst = nullptr;
    if ((long long)out_size >= outN + attnN) { hasAttn = 1; Pdst = out + outN; }
    else if ((long long)out_size == attnN)   { hasOut = 0; hasAttn = 1; Pdst = out; }

    cudaFuncSetAttribute(attn_kernel,
                         cudaFuncAttributeMaxDynamicSharedMemorySize, ATTN_SMEM);

    dim3 gg(D_ / 128, M_ / 128);  // (8, 32)
    gemm_tc_kernel<<<gg, 256>>>(query, Wq, bq, nullptr, 1);
    gemm_tc_kernel<<<gg, 256>>>(key_,  Wk, bk, nullptr, 2);
    gemm_tc_kernel<<<gg, 256>>>(value, Wv, bv, nullptr, 3);

    attn_kernel<<<dim3(NQT2_, BH_), 256, ATTN_SMEM>>>(Pdst, hasAttn);

    if (hasOut) gemm_tc_kernel<<<gg, 256>>>(nullptr, Wo, bo, out, 4);
}

// round 8
// speedup vs baseline: 1.1120x; 1.0953x over previous
#include <cuda_runtime.h>
#include <cstdint>

// ---------------- problem constants ----------------
static constexpr int B_   = 2;
static constexpr int S_   = 2048;
static constexpr int D_   = 1024;
static constexpr int H_   = 16;
static constexpr int HD_  = 64;
static constexpr int M_   = B_ * S_;    // 4096
static constexpr int BH_  = B_ * H_;    // 32
static constexpr int QT_  = 128;        // attn q-tile rows
static constexpr int NQT2_ = S_ / QT_;  // 16
static constexpr float INV_SCALE = 0.125f;  // 1/sqrt(64), exact power of 2

// ---------------- device scratch ----------------
// tf32-converted copies of inputs (written by convert_kernel)
__device__ __align__(256) float g_xq[(size_t)M_ * D_];
__device__ __align__(256) float g_xk[(size_t)M_ * D_];
__device__ __align__(256) float g_xv[(size_t)M_ * D_];
__device__ __align__(256) float g_wq[(size_t)D_ * D_];   // pre-scaled x1/8
__device__ __align__(256) float g_wk[(size_t)D_ * D_];
__device__ __align__(256) float g_wv[(size_t)D_ * D_];
__device__ __align__(256) float g_wo[(size_t)D_ * D_];
__device__ __align__(256) float g_bqs[D_];               // bq x 1/8 (fp32)
// projection outputs, stored as tf32 bits (g_q pre-scaled by 1/8)
__device__ __align__(256) float g_q [(size_t)BH_ * S_ * HD_];
__device__ __align__(256) float g_k [(size_t)BH_ * S_ * HD_];
__device__ __align__(256) float g_v [(size_t)BH_ * S_ * HD_];
__device__ __align__(256) float g_ao[(size_t)M_ * D_];   // tf32 bits

// ---------------- helpers ----------------
__device__ __forceinline__ uint32_t smem_u32(const void* p) {
    uint32_t a;
    asm("{ .reg .u64 t; cvta.to.shared.u64 t, %1; cvt.u32.u64 %0, t; }" : "=r"(a) : "l"(p));
    return a;
}
__device__ __forceinline__ void cp_async16(uint32_t saddr, const void* gaddr) {
    asm volatile("cp.async.cg.shared.global [%0], [%1], 16;" :: "r"(saddr), "l"(gaddr));
}
__device__ __forceinline__ uint32_t f2tf(float f) {
    uint32_t u;
    asm("cvt.rna.tf32.f32 %0, %1;" : "=r"(u) : "f"(f));
    return u;
}
// C += A(16x8 row) * B(8x8 col), tf32
__device__ __forceinline__ void mma8(float* c, uint32_t a0, uint32_t a1, uint32_t a2,
                                     uint32_t a3, uint32_t b0, uint32_t b1) {
    asm volatile(
        "mma.sync.aligned.m16n8k8.row.col.f32.tf32.tf32.f32 "
        "{%0,%1,%2,%3}, {%4,%5,%6,%7}, {%8,%9}, {%0,%1,%2,%3};"
        : "+f"(c[0]), "+f"(c[1]), "+f"(c[2]), "+f"(c[3])
        : "r"(a0), "r"(a1), "r"(a2), "r"(a3), "r"(b0), "r"(b1));
}

// ============================================================
// Pre-conversion: fp32 -> tf32 bits for all GEMM operands.
// Wq and bq additionally scaled by 1/8 (exact).
// Destinations are device globals referenced IN DEVICE CODE.
// ============================================================
__global__ __launch_bounds__(256) void convert_kernel(
    const float4* __restrict__ q, const float4* __restrict__ k,
    const float4* __restrict__ v, const float4* __restrict__ wq,
    const float4* __restrict__ wk, const float4* __restrict__ wv,
    const float4* __restrict__ wo, const float4* __restrict__ bq)
{
    constexpr int NQ4 = M_ * D_ / 4;   // 1048576
    constexpr int NW4 = D_ * D_ / 4;   // 262144
    constexpr int NB4 = D_ / 4;        // 256
    constexpr int TOT = 3 * NQ4 + 4 * NW4 + NB4;

    for (int i = blockIdx.x * blockDim.x + threadIdx.x; i < TOT;
         i += gridDim.x * blockDim.x) {
        int j = i;
        const float4* src; float4* dst; float sc = 1.f; bool cvt = true;
        if (j < NQ4)                    { src = q;  dst = (float4*)g_xq; }
        else if ((j -= NQ4) < NQ4)      { src = k;  dst = (float4*)g_xk; }
        else if ((j -= NQ4) < NQ4)      { src = v;  dst = (float4*)g_xv; }
        else if ((j -= NQ4) < NW4)      { src = wq; dst = (float4*)g_wq; sc = INV_SCALE; }
        else if ((j -= NW4) < NW4)      { src = wk; dst = (float4*)g_wk; }
        else if ((j -= NW4) < NW4)      { src = wv; dst = (float4*)g_wv; }
        else if ((j -= NW4) < NW4)      { src = wo; dst = (float4*)g_wo; }
        else { j -= NW4;                  src = bq; dst = (float4*)g_bqs;
               sc = INV_SCALE; cvt = false; }
        float4 s = src[j];
        float4 o;
        if (cvt) {
            o.x = __uint_as_float(f2tf(s.x * sc));
            o.y = __uint_as_float(f2tf(s.y * sc));
            o.z = __uint_as_float(f2tf(s.z * sc));
            o.w = __uint_as_float(f2tf(s.w * sc));
        } else {
            o.x = s.x * sc; o.y = s.y * sc; o.z = s.z * sc; o.w = s.w * sc;
        }
        dst[j] = o;
    }
}

// ============================================================
// tf32 mma GEMM: C[M,N] = A[M,K] @ W[N,K]^T + bias[N]
// Operands are PRE-CONVERTED tf32 bits -> no cvt in inner loop.
// A/W selected INSIDE the kernel from mode (device globals):
//   mode 1: A=g_xq W=g_wq bias=g_bqs -> g_q (tf32 bits, reshaped)
//   mode 2: A=g_xk W=g_wk bias=ext   -> g_k
//   mode 3: A=g_xv W=g_wv bias=ext   -> g_v
//   mode 0: A=g_ao W=g_wo bias=ext   -> outPlain (fp32)
// ============================================================
static constexpr int SA_ = 20;

__global__ __launch_bounds__(256, 2) void gemm_tc_kernel(
    const float* __restrict__ biasExt, float* __restrict__ outPlain, int mode)
{
    __shared__ float As[2][128 * SA_];
    __shared__ float Bs[2][128 * SA_];

    const float* A = (mode == 1) ? g_xq : (mode == 2) ? g_xk
                   : (mode == 3) ? g_xv : g_ao;
    const float* W = (mode == 1) ? g_wq : (mode == 2) ? g_wk
                   : (mode == 3) ? g_wv : g_wo;
    const float* bias = (mode == 1) ? g_bqs : biasExt;

    const int tid  = threadIdx.x;
    const int lane = tid & 31;
    const int w    = tid >> 5;
    const int gg   = lane >> 2;
    const int t4   = lane & 3;
    const int wm   = w & 1;
    const int wn   = w >> 1;
    const int rowBase = blockIdx.y * 128;
    const int colBase = blockIdx.x * 128;
    const int K = D_;

    const uint32_t sA = smem_u32(As);
    const uint32_t sB = smem_u32(Bs);

    auto stage = [&](int buf, int k0) {
#pragma unroll
        for (int ii = 0; ii < 2; ii++) {
            int idx = tid * 2 + ii;
            int row = idx >> 2;
            int c4  = (idx & 3) * 4;
            uint32_t off = (uint32_t)(buf * 128 * SA_ + row * SA_ + c4) * 4u;
            cp_async16(sA + off, &A[(size_t)(rowBase + row) * K + k0 + c4]);
            cp_async16(sB + off, &W[(size_t)(colBase + row) * K + k0 + c4]);
        }
        asm volatile("cp.async.commit_group;" ::: "memory");
    };

    float c[4][4][4];
#pragma unroll
    for (int i = 0; i < 4; i++)
#pragma unroll
        for (int j = 0; j < 4; j++)
#pragma unroll
            for (int q = 0; q < 4; q++) c[i][j][q] = 0.f;

    stage(0, 0);
    stage(1, 16);

    const int NCH = K / 16;  // 64
    for (int ch = 0; ch < NCH; ch++) {
        const int buf = ch & 1;
        if (ch < NCH - 1) asm volatile("cp.async.wait_group 1;" ::: "memory");
        else              asm volatile("cp.async.wait_group 0;" ::: "memory");
        __syncthreads();

        const float* Ab = As[buf];
        const float* Bb = Bs[buf];
#pragma unroll
        for (int kk = 0; kk < 16; kk += 8) {
            uint32_t af[4][4], bf[4][2];
#pragma unroll
            for (int i = 0; i < 4; i++) {
                int r0 = wm * 64 + i * 16 + gg;
                af[i][0] = __float_as_uint(Ab[r0 * SA_ + kk + t4]);
                af[i][1] = __float_as_uint(Ab[(r0 + 8) * SA_ + kk + t4]);
                af[i][2] = __float_as_uint(Ab[r0 * SA_ + kk + t4 + 4]);
                af[i][3] = __float_as_uint(Ab[(r0 + 8) * SA_ + kk + t4 + 4]);
            }
#pragma unroll
            for (int j = 0; j < 4; j++) {
                int n0 = wn * 32 + j * 8 + gg;
                bf[j][0] = __float_as_uint(Bb[n0 * SA_ + kk + t4]);
                bf[j][1] = __float_as_uint(Bb[n0 * SA_ + kk + t4 + 4]);
            }
#pragma unroll
            for (int i = 0; i < 4; i++)
#pragma unroll
                for (int j = 0; j < 4; j++)
                    mma8(c[i][j], af[i][0], af[i][1], af[i][2], af[i][3],
                         bf[j][0], bf[j][1]);
        }
        __syncthreads();
        if (ch + 2 < NCH) stage(buf, (ch + 2) * 16);
    }

    float* tgt = (mode == 1) ? g_q : (mode == 2) ? g_k : (mode == 3) ? g_v : outPlain;
#pragma unroll
    for (int i = 0; i < 4; i++) {
#pragma unroll
        for (int j = 0; j < 4; j++) {
            int r0  = rowBase + wm * 64 + i * 16 + gg;
            int col = colBase + wn * 32 + j * 8 + 2 * t4;
            float2 b2 = *(const float2*)&bias[col];
#pragma unroll
            for (int h = 0; h < 2; h++) {
                int m = r0 + h * 8;
                float x = c[i][j][h * 2 + 0] + b2.x;
                float y = c[i][j][h * 2 + 1] + b2.y;
                if (mode == 0) {
                    *(float2*)&tgt[(size_t)m * D_ + col] = make_float2(x, y);
                } else {
                    // store tf32 bits for downstream cvt-free MMA
                    float2 v = make_float2(__uint_as_float(f2tf(x)),
                                           __uint_as_float(f2tf(y)));
                    int bb = m >> 11, ss = m & (S_ - 1);
                    int hh = col >> 6, hd = col & 63;
                    *(float2*)&tgt[(((size_t)(bb * H_ + hh)) * S_ + ss) * HD_ + hd] = v;
                }
            }
        }
    }
}

// ============================================================
// Fused causal attention, two sweeps, PAIRED q-tiles per CTA.
// CTA handles qt = 15-bx and qt = bx -> uniform work (34 k-tiles).
// 256 threads, 8 warps (4m x 2n over 128x64 S tile).
// Q/K/V in gmem are tf32 bits (Q pre-scaled) -> staging = cp.async copy.
// Sweep 1: Q frags in registers -> rowsums.
// Sweep 2: recompute S, e_norm = exp*inv (fp32), write P once, O += E @ V.
// ============================================================
static constexpr int SQ_ = 68;
static constexpr int SV_ = 72;
static constexpr int ATTN_SMEM = (2 * QT_ * SQ_ + 64 * SV_ + 128) * 4;  // 88576 B

__global__ __launch_bounds__(256, 2) void attn_kernel(float* __restrict__ P, int writeP)
{
    extern __shared__ float sm[];
    float* Qs    = sm;                      // [128][SQ_] tf32 bits (pre-scaled)
    float* KE    = sm + QT_ * SQ_;          // K tf32 bits (rows 0..63) / E fp32
    float* Vs    = sm + 2 * QT_ * SQ_;      // [64][SV_] tf32 bits (+ rowsum scratch)
    float* inv_s = Vs + 64 * SV_;           // [128]

    const int tid  = threadIdx.x;
    const int lane = tid & 31;
    const int w    = tid >> 5;
    const int gg   = lane >> 2;
    const int t4   = lane & 3;
    const int wm   = w & 3;
    const int wn   = w >> 2;
    const int bh   = blockIdx.y;

    const float* Qg = g_q + (size_t)bh * S_ * HD_;
    const float* Kg = g_k + (size_t)bh * S_ * HD_;
    const float* Vg = g_v + (size_t)bh * S_ * HD_;

    const uint32_t sQ = smem_u32(Qs);
    const uint32_t sK = smem_u32(KE);
    const uint32_t sV = smem_u32(Vs);

#pragma unroll 1
    for (int p = 0; p < 2; p++) {
        const int qt = p == 0 ? (NQT2_ - 1) - (int)blockIdx.x : (int)blockIdx.x;
        const int q0 = qt * QT_;
        __syncthreads();  // previous pair's readers of Qs done

        // stage Q tile: pure cp.async copy (already tf32 + pre-scaled)
#pragma unroll
        for (int i = 0; i < 8; i++) {
            int idx = tid + i * 256;
            int row = idx >> 4, cc = (idx & 15) * 4;
            cp_async16(sQ + (uint32_t)(row * SQ_ + cc) * 4u,
                       &Qg[(size_t)(q0 + row) * HD_ + cc]);
        }
        asm volatile("cp.async.commit_group;" ::: "memory");
        asm volatile("cp.async.wait_group 0;" ::: "memory");
        __syncthreads();

        // Q fragments -> registers (invariant across k-tiles)
        uint32_t qf[8][8];
#pragma unroll
        for (int kk = 0; kk < 8; kk++) {
#pragma unroll
            for (int i = 0; i < 2; i++) {
                int r0 = wm * 32 + i * 16 + gg;
                qf[kk][i * 4 + 0] = __float_as_uint(Qs[r0 * SQ_ + kk * 8 + t4]);
                qf[kk][i * 4 + 1] = __float_as_uint(Qs[(r0 + 8) * SQ_ + kk * 8 + t4]);
                qf[kk][i * 4 + 2] = __float_as_uint(Qs[r0 * SQ_ + kk * 8 + t4 + 4]);
                qf[kk][i * 4 + 3] = __float_as_uint(Qs[(r0 + 8) * SQ_ + kk * 8 + t4 + 4]);
            }
        }

        const int nkt = 2 * qt + 2;

        // ================= sweep 1: rowsums =================
        float rs[2][2] = {{0.f, 0.f}, {0.f, 0.f}};
        for (int kt = 0; kt < nkt; kt++) {
            const int k0 = kt * 64;
            __syncthreads();
#pragma unroll
            for (int i = 0; i < 4; i++) {
                int idx = tid + i * 256;
                int row = idx >> 4, cc = (idx & 15) * 4;
                cp_async16(sK + (uint32_t)(row * SQ_ + cc) * 4u,
                           &Kg[(size_t)(k0 + row) * HD_ + cc]);
            }
            asm volatile("cp.async.commit_group;" ::: "memory");
            asm volatile("cp.async.wait_group 0;" ::: "memory");
            __syncthreads();

            float s[2][4][4];
#pragma unroll
            for (int i = 0; i < 2; i++)
#pragma unroll
                for (int j = 0; j < 4; j++)
#pragma unroll
                    for (int q = 0; q < 4; q++) s[i][j][q] = 0.f;
#pragma unroll
            for (int kk = 0; kk < 8; kk++) {
                uint32_t bf[4][2];
#pragma unroll
                for (int j = 0; j < 4; j++) {
                    int n0 = wn * 32 + j * 8 + gg;
                    bf[j][0] = __float_as_uint(KE[n0 * SQ_ + kk * 8 + t4]);
                    bf[j][1] = __float_as_uint(KE[n0 * SQ_ + kk * 8 + t4 + 4]);
                }
#pragma unroll
                for (int i = 0; i < 2; i++)
#pragma unroll
                    for (int j = 0; j < 4; j++)
                        mma8(s[i][j], qf[kk][i * 4 + 0], qf[kk][i * 4 + 1],
                             qf[kk][i * 4 + 2], qf[kk][i * 4 + 3], bf[j][0], bf[j][1]);
            }

            if (k0 + 63 <= q0 + wm * 32) {
#pragma unroll
                for (int i = 0; i < 2; i++)
#pragma unroll
                    for (int j = 0; j < 4; j++) {
                        rs[i][0] += __expf(s[i][j][0]) + __expf(s[i][j][1]);
                        rs[i][1] += __expf(s[i][j][2]) + __expf(s[i][j][3]);
                    }
            } else {
#pragma unroll
                for (int i = 0; i < 2; i++) {
                    int qiA = q0 + wm * 32 + i * 16 + gg, qiB = qiA + 8;
#pragma unroll
                    for (int j = 0; j < 4; j++) {
                        int ki0 = k0 + wn * 32 + j * 8 + 2 * t4, ki1 = ki0 + 1;
                        rs[i][0] += ((ki0 <= qiA) ? __expf(s[i][j][0]) : 0.f)
                                  + ((ki1 <= qiA) ? __expf(s[i][j][1]) : 0.f);
                        rs[i][1] += ((ki0 <= qiB) ? __expf(s[i][j][2]) : 0.f)
                                  + ((ki1 <= qiB) ? __expf(s[i][j][3]) : 0.f);
                    }
                }
            }
        }
        // reduce rowsums
#pragma unroll
        for (int i = 0; i < 2; i++) {
#pragma unroll
            for (int h = 0; h < 2; h++) {
                rs[i][h] += __shfl_xor_sync(0xFFFFFFFF, rs[i][h], 1);
                rs[i][h] += __shfl_xor_sync(0xFFFFFFFF, rs[i][h], 2);
            }
        }
        __syncthreads();
        if (t4 == 0) {
#pragma unroll
            for (int i = 0; i < 2; i++) {
                int r0 = wm * 32 + i * 16 + gg;
                Vs[wn * 128 + r0]     = rs[i][0];
                Vs[wn * 128 + r0 + 8] = rs[i][1];
            }
        }
        __syncthreads();
        if (tid < 128) inv_s[tid] = 1.f / (Vs[tid] + Vs[128 + tid]);
        __syncthreads();

        // ================= sweep 2: P + O =================
        float o[2][4][4];
#pragma unroll
        for (int i = 0; i < 2; i++)
#pragma unroll
            for (int j = 0; j < 4; j++)
#pragma unroll
                for (int q = 0; q < 4; q++) o[i][j][q] = 0.f;

        for (int kt = 0; kt < S_ / 64; kt++) {
            const int k0 = kt * 64;
            if (kt < nkt) {
                __syncthreads();
#pragma unroll
                for (int i = 0; i < 4; i++) {
                    int idx = tid + i * 256;
                    int row = idx >> 4, cc = (idx & 15) * 4;
                    cp_async16(sK + (uint32_t)(row * SQ_ + cc) * 4u,
                               &Kg[(size_t)(k0 + row) * HD_ + cc]);
                    cp_async16(sV + (uint32_t)(row * SV_ + cc) * 4u,
                               &Vg[(size_t)(k0 + row) * HD_ + cc]);
                }
                asm volatile("cp.async.commit_group;" ::: "memory");
                asm volatile("cp.async.wait_group 0;" ::: "memory");
                __syncthreads();

                float s[2][4][4];
#pragma unroll
                for (int i = 0; i < 2; i++)
#pragma unroll
                    for (int j = 0; j < 4; j++)
#pragma unroll
                        for (int q = 0; q < 4; q++) s[i][j][q] = 0.f;
#pragma unroll
                for (int kk = 0; kk < 8; kk++) {
                    uint32_t bf[4][2];
#pragma unroll
                    for (int j = 0; j < 4; j++) {
                        int n0 = wn * 32 + j * 8 + gg;
                        bf[j][0] = __float_as_uint(KE[n0 * SQ_ + kk * 8 + t4]);
                        bf[j][1] = __float_as_uint(KE[n0 * SQ_ + kk * 8 + t4 + 4]);
                    }
#pragma unroll
                    for (int i = 0; i < 2; i++)
#pragma unroll
                        for (int j = 0; j < 4; j++)
                            mma8(s[i][j], qf[kk][i * 4 + 0], qf[kk][i * 4 + 1],
                                 qf[kk][i * 4 + 2], qf[kk][i * 4 + 3],
                                 bf[j][0], bf[j][1]);
                }

                // e_norm = exp * inv (fp32), masked only on edge tiles
#pragma unroll
                for (int i = 0; i < 2; i++) {
                    int r0 = wm * 32 + i * 16 + gg;
                    float invA = inv_s[r0], invB = inv_s[r0 + 8];
                    if (k0 + 63 <= q0 + wm * 32) {
#pragma unroll
                        for (int j = 0; j < 4; j++) {
                            s[i][j][0] = __expf(s[i][j][0]) * invA;
                            s[i][j][1] = __expf(s[i][j][1]) * invA;
                            s[i][j][2] = __expf(s[i][j][2]) * invB;
                            s[i][j][3] = __expf(s[i][j][3]) * invB;
                        }
                    } else {
                        int qiA = q0 + r0, qiB = qiA + 8;
#pragma unroll
                        for (int j = 0; j < 4; j++) {
                            int ki0 = k0 + wn * 32 + j * 8 + 2 * t4, ki1 = ki0 + 1;
                            s[i][j][0] = (ki0 <= qiA) ? __expf(s[i][j][0]) * invA : 0.f;
                            s[i][j][1] = (ki1 <= qiA) ? __expf(s[i][j][1]) * invA : 0.f;
                            s[i][j][2] = (ki0 <= qiB) ? __expf(s[i][j][2]) * invB : 0.f;
                            s[i][j][3] = (ki1 <= qiB) ? __expf(s[i][j][3]) * invB : 0.f;
                        }
                    }
                }
                __syncthreads();

                // store E (fp32) into KE
#pragma unroll
                for (int i = 0; i < 2; i++) {
                    int r0 = wm * 32 + i * 16 + gg;
#pragma unroll
                    for (int j = 0; j < 4; j++) {
                        int cl = wn * 32 + j * 8 + 2 * t4;
                        *(float2*)&KE[r0 * SQ_ + cl]       = make_float2(s[i][j][0], s[i][j][1]);
                        *(float2*)&KE[(r0 + 8) * SQ_ + cl] = make_float2(s[i][j][2], s[i][j][3]);
                    }
                }
                __syncthreads();

                // coalesced write of NORMALIZED P
                if (writeP) {
                    float* Pd = P + (size_t)bh * S_ * S_ + (size_t)q0 * S_ + k0;
#pragma unroll
                    for (int i = 0; i < 8; i++) {
                        int idx = tid + i * 256;
                        int row = idx >> 4, cc = (idx & 15) * 4;
                        *(float4*)&Pd[(size_t)row * S_ + cc] =
                            *(const float4*)&KE[row * SQ_ + cc];
                    }
                }

                // O += E_norm @ V
#pragma unroll
                for (int kk = 0; kk < 8; kk++) {
                    uint32_t af[2][4], bf[4][2];
#pragma unroll
                    for (int i = 0; i < 2; i++) {
                        int r0 = wm * 32 + i * 16 + gg;
                        af[i][0] = f2tf(KE[r0 * SQ_ + kk * 8 + t4]);
                        af[i][1] = f2tf(KE[(r0 + 8) * SQ_ + kk * 8 + t4]);
                        af[i][2] = f2tf(KE[r0 * SQ_ + kk * 8 + t4 + 4]);
                        af[i][3] = f2tf(KE[(r0 + 8) * SQ_ + kk * 8 + t4 + 4]);
                    }
#pragma unroll
                    for (int j = 0; j < 4; j++) {
                        int n0 = wn * 32 + j * 8 + gg;
                        bf[j][0] = __float_as_uint(Vs[(kk * 8 + t4) * SV_ + n0]);
                        bf[j][1] = __float_as_uint(Vs[(kk * 8 + t4 + 4) * SV_ + n0]);
                    }
#pragma unroll
                    for (int i = 0; i < 2; i++)
#pragma unroll
                        for (int j = 0; j < 4; j++)
                            mma8(o[i][j], af[i][0], af[i][1], af[i][2], af[i][3],
                                 bf[j][0], bf[j][1]);
                }
            } else if (writeP) {
                // fully-masked tile: zero-fill P
                float* Pd = P + (size_t)bh * S_ * S_ + (size_t)q0 * S_ + k0;
                const float4 z = make_float4(0.f, 0.f, 0.f, 0.f);
#pragma unroll
                for (int i = 0; i < 8; i++) {
                    int idx = tid + i * 256;
                    int row = idx >> 4, cc = (idx & 15) * 4;
                    *(float4*)&Pd[(size_t)row * S_ + cc] = z;
                }
            }
        }

        // epilogue: O normalized; store as tf32 bits (feeds cvt-free final GEMM)
        const int bb = bh >> 4, hh = bh & 15;
#pragma unroll
        for (int i = 0; i < 2; i++) {
            int r0 = wm * 32 + i * 16 + gg;
            int mA = bb * S_ + q0 + r0;
#pragma unroll
            for (int j = 0; j < 4; j++) {
                int cl = hh * 64 + wn * 32 + j * 8 + 2 * t4;
                *(float2*)&g_ao[(size_t)mA * D_ + cl] =
                    make_float2(__uint_as_float(f2tf(o[i][j][0])),
                                __uint_as_float(f2tf(o[i][j][1])));
                *(float2*)&g_ao[(size_t)(mA + 8) * D_ + cl] =
                    make_float2(__uint_as_float(f2tf(o[i][j][2])),
                                __uint_as_float(f2tf(o[i][j][3])));
            }
        }
    }
}

// ============================================================
extern "C" void kernel_launch(void* const* d_in, const int* in_sizes, int n_in,
                              void* d_out, int out_size)
{
    const float* query = (const float*)d_in[0];
    const float* key_  = (const float*)d_in[1];
    const float* value = (const float*)d_in[2];
    // d_in[3] = causal mask — handled analytically
    const float* Wq = (const float*)d_in[4];
    const float* bq = (const float*)d_in[5];
    const float* Wk = (const float*)d_in[6];
    const float* bk = (const float*)d_in[7];
    const float* Wv = (const float*)d_in[8];
    const float* bv = (const float*)d_in[9];
    const float* Wo = (const float*)d_in[10];
    const float* bo = (const float*)d_in[11];
    float* out = (float*)d_out;

    const long long outN  = (long long)M_ * D_;
    const long long attnN = (long long)BH_ * S_ * S_;

    int hasOut = 1, hasAttn = 0;
    float* Pdst = nullptr;
    if ((long long)out_size >= outN + attnN) { hasAttn = 1; Pdst = out + outN; }
    else if ((long long)out_size == attnN)   { hasOut = 0; hasAttn = 1; Pdst = out; }

    cudaFuncSetAttribute(attn_kernel,
                         cudaFuncAttributeMaxDynamicSharedMemorySize, ATTN_SMEM);

    convert_kernel<<<512, 256>>>(
        (const float4*)query, (const float4*)key_, (const float4*)value,
        (const float4*)Wq, (const float4*)Wk, (const float4*)Wv,
        (const float4*)Wo, (const float4*)bq);

    dim3 gg(D_ / 128, M_ / 128);  // (8, 32)
    gemm_tc_kernel<<<gg, 256>>>(nullptr, nullptr, 1);
    gemm_tc_kernel<<<gg, 256>>>(bk, nullptr, 2);
    gemm_tc_kernel<<<gg, 256>>>(bv, nullptr, 3);

    attn_kernel<<<dim3(NQT2_ / 2, BH_), 256, ATTN_SMEM>>>(Pdst, hasAttn);

    if (hasOut) gemm_tc_kernel<<<gg, 256>>>(bo, out, 0);
}

// round 9
// speedup vs baseline: 1.1713x; 1.0533x over previous
#include <cuda_runtime.h>
#include <cstdint>

// ---------------- problem constants ----------------
static constexpr int B_   = 2;
static constexpr int S_   = 2048;
static constexpr int D_   = 1024;
static constexpr int H_   = 16;
static constexpr int HD_  = 64;
static constexpr int M_   = B_ * S_;    // 4096
static constexpr int BH_  = B_ * H_;    // 32
static constexpr int QT_  = 128;        // attn q-tile rows
static constexpr int NQT2_ = S_ / QT_;  // 16
static constexpr float INV_SCALE = 0.125f;  // 1/sqrt(64), exact power of 2

// ---------------- device scratch ----------------
__device__ __align__(256) float g_xq[(size_t)M_ * D_];
__device__ __align__(256) float g_xk[(size_t)M_ * D_];
__device__ __align__(256) float g_xv[(size_t)M_ * D_];
__device__ __align__(256) float g_wq[(size_t)D_ * D_];   // pre-scaled x1/8
__device__ __align__(256) float g_wk[(size_t)D_ * D_];
__device__ __align__(256) float g_wv[(size_t)D_ * D_];
__device__ __align__(256) float g_wo[(size_t)D_ * D_];
__device__ __align__(256) float g_bqs[D_];               // bq x 1/8 (fp32)
__device__ __align__(256) float g_q [(size_t)BH_ * S_ * HD_];  // tf32 bits, pre-scaled
__device__ __align__(256) float g_k [(size_t)BH_ * S_ * HD_];  // tf32 bits
__device__ __align__(256) float g_v [(size_t)BH_ * S_ * HD_];  // tf32 bits
__device__ __align__(256) float g_ao[(size_t)M_ * D_];         // tf32 bits

// ---------------- helpers ----------------
__device__ __forceinline__ uint32_t smem_u32(const void* p) {
    uint32_t a;
    asm("{ .reg .u64 t; cvta.to.shared.u64 t, %1; cvt.u32.u64 %0, t; }" : "=r"(a) : "l"(p));
    return a;
}
__device__ __forceinline__ void cp_async16(uint32_t saddr, const void* gaddr) {
    asm volatile("cp.async.cg.shared.global [%0], [%1], 16;" :: "r"(saddr), "l"(gaddr));
}
__device__ __forceinline__ uint32_t f2tf(float f) {
    uint32_t u;
    asm("cvt.rna.tf32.f32 %0, %1;" : "=r"(u) : "f"(f));
    return u;
}
__device__ __forceinline__ void mma8(float* c, uint32_t a0, uint32_t a1, uint32_t a2,
                                     uint32_t a3, uint32_t b0, uint32_t b1) {
    asm volatile(
        "mma.sync.aligned.m16n8k8.row.col.f32.tf32.tf32.f32 "
        "{%0,%1,%2,%3}, {%4,%5,%6,%7}, {%8,%9}, {%0,%1,%2,%3};"
        : "+f"(c[0]), "+f"(c[1]), "+f"(c[2]), "+f"(c[3])
        : "r"(a0), "r"(a1), "r"(a2), "r"(a3), "r"(b0), "r"(b1));
}

// ============================================================
// Pre-conversion: fp32 -> tf32 bits. Wq,bq scaled by 1/8 (exact).
// ============================================================
__global__ __launch_bounds__(256) void convert_kernel(
    const float4* __restrict__ q, const float4* __restrict__ k,
    const float4* __restrict__ v, const float4* __restrict__ wq,
    const float4* __restrict__ wk, const float4* __restrict__ wv,
    const float4* __restrict__ wo, const float4* __restrict__ bq)
{
    constexpr int NQ4 = M_ * D_ / 4;
    constexpr int NW4 = D_ * D_ / 4;
    constexpr int NB4 = D_ / 4;
    constexpr int TOT = 3 * NQ4 + 4 * NW4 + NB4;

    for (int i = blockIdx.x * blockDim.x + threadIdx.x; i < TOT;
         i += gridDim.x * blockDim.x) {
        int j = i;
        const float4* src; float4* dst; float sc = 1.f; bool cvt = true;
        if (j < NQ4)                    { src = q;  dst = (float4*)g_xq; }
        else if ((j -= NQ4) < NQ4)      { src = k;  dst = (float4*)g_xk; }
        else if ((j -= NQ4) < NQ4)      { src = v;  dst = (float4*)g_xv; }
        else if ((j -= NQ4) < NW4)      { src = wq; dst = (float4*)g_wq; sc = INV_SCALE; }
        else if ((j -= NW4) < NW4)      { src = wk; dst = (float4*)g_wk; }
        else if ((j -= NW4) < NW4)      { src = wv; dst = (float4*)g_wv; }
        else if ((j -= NW4) < NW4)      { src = wo; dst = (float4*)g_wo; }
        else { j -= NW4;                  src = bq; dst = (float4*)g_bqs;
               sc = INV_SCALE; cvt = false; }
        float4 s = src[j];
        float4 o;
        if (cvt) {
            o.x = __uint_as_float(f2tf(s.x * sc));
            o.y = __uint_as_float(f2tf(s.y * sc));
            o.z = __uint_as_float(f2tf(s.z * sc));
            o.w = __uint_as_float(f2tf(s.w * sc));
        } else {
            o.x = s.x * sc; o.y = s.y * sc; o.z = s.z * sc; o.w = s.w * sc;
        }
        dst[j] = o;
    }
}

// ============================================================
// tf32 mma GEMM, 3-buffer single-sync pipeline.
//   modeParam==99: fused QKV, mode = blockIdx.z + 1
//   mode 1: g_xq@g_wq + g_bqs -> g_q ; 2: g_xk@g_wk+bk -> g_k ;
//   mode 3: g_xv@g_wv+bv -> g_v ; 0: g_ao@g_wo+bo -> out (fp32)
// ============================================================
static constexpr int SA_ = 20;
static constexpr int GEMM_SMEM = 3 * 2 * 128 * SA_ * 4;  // 61440 B

__global__ __launch_bounds__(256, 2) void gemm_tc_kernel(
    const float* __restrict__ biasK, const float* __restrict__ biasV,
    const float* __restrict__ biasO, float* __restrict__ outPlain, int modeParam)
{
    extern __shared__ float smg[];
    float* As = smg;                    // [3][128*SA_]
    float* Bs = smg + 3 * 128 * SA_;

    const int mode = (modeParam == 99) ? (int)blockIdx.z + 1 : modeParam;
    const float* A = (mode == 1) ? g_xq : (mode == 2) ? g_xk
                   : (mode == 3) ? g_xv : g_ao;
    const float* W = (mode == 1) ? g_wq : (mode == 2) ? g_wk
                   : (mode == 3) ? g_wv : g_wo;
    const float* bias = (mode == 1) ? g_bqs : (mode == 2) ? biasK
                      : (mode == 3) ? biasV : biasO;

    const int tid  = threadIdx.x;
    const int lane = tid & 31;
    const int w    = tid >> 5;
    const int gg   = lane >> 2;
    const int t4   = lane & 3;
    const int wm   = w & 1;
    const int wn   = w >> 1;
    const int rowBase = blockIdx.y * 128;
    const int colBase = blockIdx.x * 128;
    const int K = D_;

    const uint32_t sA = smem_u32(As);
    const uint32_t sB = smem_u32(Bs);

    auto stage = [&](int st, int k0) {
#pragma unroll
        for (int ii = 0; ii < 2; ii++) {
            int idx = tid * 2 + ii;
            int row = idx >> 2;
            int c4  = (idx & 3) * 4;
            uint32_t off = (uint32_t)(st * 128 * SA_ + row * SA_ + c4) * 4u;
            cp_async16(sA + off, &A[(size_t)(rowBase + row) * K + k0 + c4]);
            cp_async16(sB + off, &W[(size_t)(colBase + row) * K + k0 + c4]);
        }
        asm volatile("cp.async.commit_group;" ::: "memory");
    };

    float c[4][4][4];
#pragma unroll
    for (int i = 0; i < 4; i++)
#pragma unroll
        for (int j = 0; j < 4; j++)
#pragma unroll
            for (int q = 0; q < 4; q++) c[i][j][q] = 0.f;

    const int NCH = K / 16;  // 64
    stage(0, 0);
    stage(1, 16);

    for (int ch = 0; ch < NCH; ch++) {
        if (ch < NCH - 1) asm volatile("cp.async.wait_group 1;" ::: "memory");
        else              asm volatile("cp.async.wait_group 0;" ::: "memory");
        __syncthreads();
        if (ch + 2 < NCH) stage((ch + 2) % 3, (ch + 2) * 16);  // overlaps MMA below

        const float* Ab = As + (ch % 3) * 128 * SA_;
        const float* Bb = Bs + (ch % 3) * 128 * SA_;
#pragma unroll
        for (int kk = 0; kk < 16; kk += 8) {
            uint32_t af[4][4], bf[4][2];
#pragma unroll
            for (int i = 0; i < 4; i++) {
                int r0 = wm * 64 + i * 16 + gg;
                af[i][0] = __float_as_uint(Ab[r0 * SA_ + kk + t4]);
                af[i][1] = __float_as_uint(Ab[(r0 + 8) * SA_ + kk + t4]);
                af[i][2] = __float_as_uint(Ab[r0 * SA_ + kk + t4 + 4]);
                af[i][3] = __float_as_uint(Ab[(r0 + 8) * SA_ + kk + t4 + 4]);
            }
#pragma unroll
            for (int j = 0; j < 4; j++) {
                int n0 = wn * 32 + j * 8 + gg;
                bf[j][0] = __float_as_uint(Bb[n0 * SA_ + kk + t4]);
                bf[j][1] = __float_as_uint(Bb[n0 * SA_ + kk + t4 + 4]);
            }
#pragma unroll
            for (int i = 0; i < 4; i++)
#pragma unroll
                for (int j = 0; j < 4; j++)
                    mma8(c[i][j], af[i][0], af[i][1], af[i][2], af[i][3],
                         bf[j][0], bf[j][1]);
        }
    }

    float* tgt = (mode == 1) ? g_q : (mode == 2) ? g_k : (mode == 3) ? g_v : outPlain;
#pragma unroll
    for (int i = 0; i < 4; i++) {
#pragma unroll
        for (int j = 0; j < 4; j++) {
            int r0  = rowBase + wm * 64 + i * 16 + gg;
            int col = colBase + wn * 32 + j * 8 + 2 * t4;
            float2 b2 = *(const float2*)&bias[col];
#pragma unroll
            for (int h = 0; h < 2; h++) {
                int m = r0 + h * 8;
                float x = c[i][j][h * 2 + 0] + b2.x;
                float y = c[i][j][h * 2 + 1] + b2.y;
                if (mode == 0) {
                    *(float2*)&tgt[(size_t)m * D_ + col] = make_float2(x, y);
                } else {
                    float2 v = make_float2(__uint_as_float(f2tf(x)),
                                           __uint_as_float(f2tf(y)));
                    int bb = m >> 11, ss = m & (S_ - 1);
                    int hh = col >> 6, hd = col & 63;
                    *(float2*)&tgt[(((size_t)(bb * H_ + hh)) * S_ + ss) * HD_ + hd] = v;
                }
            }
        }
    }
}

// ============================================================
// Fused causal attention, two sweeps, paired q-tiles, double-buffered
// K (sweep1) and K+V (sweep2). E lives in the Qs region (Q is in regs).
// ============================================================
static constexpr int SQ_ = 68;
static constexpr int SV_ = 72;
// QsE [128][SQ_] + Kdb 2x[64][SQ_] + Vdb 2x[64][SV_] + inv_s[128]
static constexpr int ATTN_SMEM = (2 * QT_ * SQ_ + 2 * 64 * SV_ + 128) * 4;  // 107008 B

__global__ __launch_bounds__(256, 2) void attn_kernel(float* __restrict__ P, int writeP)
{
    extern __shared__ float sm[];
    float* QsE   = sm;                        // [128][SQ_]: Q staging, then E
    float* Kdb   = sm + QT_ * SQ_;            // 2 x [64][SQ_]
    float* Vdb   = sm + 2 * QT_ * SQ_;        // 2 x [64][SV_] (+ rowsum scratch)
    float* inv_s = sm + 2 * QT_ * SQ_ + 2 * 64 * SV_;  // [128]

    const int tid  = threadIdx.x;
    const int lane = tid & 31;
    const int w    = tid >> 5;
    const int gg   = lane >> 2;
    const int t4   = lane & 3;
    const int wm   = w & 3;
    const int wn   = w >> 2;
    const int bh   = blockIdx.y;

    const float* Qg = g_q + (size_t)bh * S_ * HD_;
    const float* Kg = g_k + (size_t)bh * S_ * HD_;
    const float* Vg = g_v + (size_t)bh * S_ * HD_;

    const uint32_t sQ = smem_u32(QsE);
    const uint32_t sK = smem_u32(Kdb);
    const uint32_t sV = smem_u32(Vdb);

    auto stageK = [&](int b, int k0) {
#pragma unroll
        for (int i = 0; i < 4; i++) {
            int idx = tid + i * 256;
            int row = idx >> 4, cc = (idx & 15) * 4;
            cp_async16(sK + (uint32_t)(b * 64 * SQ_ + row * SQ_ + cc) * 4u,
                       &Kg[(size_t)(k0 + row) * HD_ + cc]);
        }
    };
    auto stageV = [&](int b, int k0) {
#pragma unroll
        for (int i = 0; i < 4; i++) {
            int idx = tid + i * 256;
            int row = idx >> 4, cc = (idx & 15) * 4;
            cp_async16(sV + (uint32_t)(b * 64 * SV_ + row * SV_ + cc) * 4u,
                       &Vg[(size_t)(k0 + row) * HD_ + cc]);
        }
    };

#pragma unroll 1
    for (int p = 0; p < 2; p++) {
        const int qt = p == 0 ? (NQT2_ - 1) - (int)blockIdx.x : (int)blockIdx.x;
        const int q0 = qt * QT_;
        __syncthreads();  // previous pair fully done (E/K/V readers)

        // stage Q tile (tf32 bits, pre-scaled)
#pragma unroll
        for (int i = 0; i < 8; i++) {
            int idx = tid + i * 256;
            int row = idx >> 4, cc = (idx & 15) * 4;
            cp_async16(sQ + (uint32_t)(row * SQ_ + cc) * 4u,
                       &Qg[(size_t)(q0 + row) * HD_ + cc]);
        }
        asm volatile("cp.async.commit_group;" ::: "memory");
        asm volatile("cp.async.wait_group 0;" ::: "memory");
        __syncthreads();

        // Q fragments -> registers
        uint32_t qf[8][8];
#pragma unroll
        for (int kk = 0; kk < 8; kk++) {
#pragma unroll
            for (int i = 0; i < 2; i++) {
                int r0 = wm * 32 + i * 16 + gg;
                qf[kk][i * 4 + 0] = __float_as_uint(QsE[r0 * SQ_ + kk * 8 + t4]);
                qf[kk][i * 4 + 1] = __float_as_uint(QsE[(r0 + 8) * SQ_ + kk * 8 + t4]);
                qf[kk][i * 4 + 2] = __float_as_uint(QsE[r0 * SQ_ + kk * 8 + t4 + 4]);
                qf[kk][i * 4 + 3] = __float_as_uint(QsE[(r0 + 8) * SQ_ + kk * 8 + t4 + 4]);
            }
        }
        __syncthreads();  // Qs region now free for E

        const int nkt = 2 * qt + 2;

        // ================= sweep 1: rowsums (K double-buffered) ========
        stageK(0, 0);
        asm volatile("cp.async.commit_group;" ::: "memory");

        float rs[2][2] = {{0.f, 0.f}, {0.f, 0.f}};
        for (int kt = 0; kt < nkt; kt++) {
            const int b = kt & 1;
            __syncthreads();  // all warps done with buffer (kt+1)&1 (iter kt-1)
            if (kt + 1 < nkt) {
                stageK(1 - b, (kt + 1) * 64);
                asm volatile("cp.async.commit_group;" ::: "memory");
                asm volatile("cp.async.wait_group 1;" ::: "memory");
            } else {
                asm volatile("cp.async.wait_group 0;" ::: "memory");
            }
            __syncthreads();  // K(kt) visible

            const float* Kb = Kdb + b * 64 * SQ_;
            float s[2][4][4];
#pragma unroll
            for (int i = 0; i < 2; i++)
#pragma unroll
                for (int j = 0; j < 4; j++)
#pragma unroll
                    for (int q = 0; q < 4; q++) s[i][j][q] = 0.f;
#pragma unroll
            for (int kk = 0; kk < 8; kk++) {
                uint32_t bf[4][2];
#pragma unroll
                for (int j = 0; j < 4; j++) {
                    int n0 = wn * 32 + j * 8 + gg;
                    bf[j][0] = __float_as_uint(Kb[n0 * SQ_ + kk * 8 + t4]);
                    bf[j][1] = __float_as_uint(Kb[n0 * SQ_ + kk * 8 + t4 + 4]);
                }
#pragma unroll
                for (int i = 0; i < 2; i++)
#pragma unroll
                    for (int j = 0; j < 4; j++)
                        mma8(s[i][j], qf[kk][i * 4 + 0], qf[kk][i * 4 + 1],
                             qf[kk][i * 4 + 2], qf[kk][i * 4 + 3], bf[j][0], bf[j][1]);
            }

            const int k0 = kt * 64;
            if (k0 + 63 <= q0 + wm * 32) {
#pragma unroll
                for (int i = 0; i < 2; i++)
#pragma unroll
                    for (int j = 0; j < 4; j++) {
                        rs[i][0] += __expf(s[i][j][0]) + __expf(s[i][j][1]);
                        rs[i][1] += __expf(s[i][j][2]) + __expf(s[i][j][3]);
                    }
            } else {
#pragma unroll
                for (int i = 0; i < 2; i++) {
                    int qiA = q0 + wm * 32 + i * 16 + gg, qiB = qiA + 8;
#pragma unroll
                    for (int j = 0; j < 4; j++) {
                        int ki0 = k0 + wn * 32 + j * 8 + 2 * t4, ki1 = ki0 + 1;
                        rs[i][0] += ((ki0 <= qiA) ? __expf(s[i][j][0]) : 0.f)
                                  + ((ki1 <= qiA) ? __expf(s[i][j][1]) : 0.f);
                        rs[i][1] += ((ki0 <= qiB) ? __expf(s[i][j][2]) : 0.f)
                                  + ((ki1 <= qiB) ? __expf(s[i][j][3]) : 0.f);
                    }
                }
            }
        }
        // reduce rowsums (Vdb buf0 as scratch)
#pragma unroll
        for (int i = 0; i < 2; i++) {
#pragma unroll
            for (int h = 0; h < 2; h++) {
                rs[i][h] += __shfl_xor_sync(0xFFFFFFFF, rs[i][h], 1);
                rs[i][h] += __shfl_xor_sync(0xFFFFFFFF, rs[i][h], 2);
            }
        }
        __syncthreads();
        if (t4 == 0) {
#pragma unroll
            for (int i = 0; i < 2; i++) {
                int r0 = wm * 32 + i * 16 + gg;
                Vdb[wn * 128 + r0]     = rs[i][0];
                Vdb[wn * 128 + r0 + 8] = rs[i][1];
            }
        }
        __syncthreads();
        if (tid < 128) inv_s[tid] = 1.f / (Vdb[tid] + Vdb[128 + tid]);
        __syncthreads();

        // ================= sweep 2: P + O (K,V double-buffered) ========
        float o[2][4][4];
#pragma unroll
        for (int i = 0; i < 2; i++)
#pragma unroll
            for (int j = 0; j < 4; j++)
#pragma unroll
                for (int q = 0; q < 4; q++) o[i][j][q] = 0.f;

        stageK(0, 0); stageV(0, 0);
        asm volatile("cp.async.commit_group;" ::: "memory");

        for (int kt = 0; kt < S_ / 64; kt++) {
            const int k0 = kt * 64;
            if (kt < nkt) {
                const int b = kt & 1;
                __syncthreads();  // prior iter consumers of buf 1-b / E done
                if (kt + 1 < nkt) {
                    stageK(1 - b, (kt + 1) * 64);
                    stageV(1 - b, (kt + 1) * 64);
                    asm volatile("cp.async.commit_group;" ::: "memory");
                    asm volatile("cp.async.wait_group 1;" ::: "memory");
                } else {
                    asm volatile("cp.async.wait_group 0;" ::: "memory");
                }
                __syncthreads();  // K/V(kt) visible

                const float* Kb = Kdb + b * 64 * SQ_;
                const float* Vb = Vdb + b * 64 * SV_;

                float s[2][4][4];
#pragma unroll
                for (int i = 0; i < 2; i++)
#pragma unroll
                    for (int j = 0; j < 4; j++)
#pragma unroll
                        for (int q = 0; q < 4; q++) s[i][j][q] = 0.f;
#pragma unroll
                for (int kk = 0; kk < 8; kk++) {
                    uint32_t bf[4][2];
#pragma unroll
                    for (int j = 0; j < 4; j++) {
                        int n0 = wn * 32 + j * 8 + gg;
                        bf[j][0] = __float_as_uint(Kb[n0 * SQ_ + kk * 8 + t4]);
                        bf[j][1] = __float_as_uint(Kb[n0 * SQ_ + kk * 8 + t4 + 4]);
                    }
#pragma unroll
                    for (int i = 0; i < 2; i++)
#pragma unroll
                        for (int j = 0; j < 4; j++)
                            mma8(s[i][j], qf[kk][i * 4 + 0], qf[kk][i * 4 + 1],
                                 qf[kk][i * 4 + 2], qf[kk][i * 4 + 3],
                                 bf[j][0], bf[j][1]);
                }

                // e_norm = exp * inv, masked only on edge tiles
#pragma unroll
                for (int i = 0; i < 2; i++) {
                    int r0 = wm * 32 + i * 16 + gg;
                    float invA = inv_s[r0], invB = inv_s[r0 + 8];
                    if (k0 + 63 <= q0 + wm * 32) {
#pragma unroll
                        for (int j = 0; j < 4; j++) {
                            s[i][j][0] = __expf(s[i][j][0]) * invA;
                            s[i][j][1] = __expf(s[i][j][1]) * invA;
                            s[i][j][2] = __expf(s[i][j][2]) * invB;
                            s[i][j][3] = __expf(s[i][j][3]) * invB;
                        }
                    } else {
                        int qiA = q0 + r0, qiB = qiA + 8;
#pragma unroll
                        for (int j = 0; j < 4; j++) {
                            int ki0 = k0 + wn * 32 + j * 8 + 2 * t4, ki1 = ki0 + 1;
                            s[i][j][0] = (ki0 <= qiA) ? __expf(s[i][j][0]) * invA : 0.f;
                            s[i][j][1] = (ki1 <= qiA) ? __expf(s[i][j][1]) * invA : 0.f;
                            s[i][j][2] = (ki0 <= qiB) ? __expf(s[i][j][2]) * invB : 0.f;
                            s[i][j][3] = (ki1 <= qiB) ? __expf(s[i][j][3]) * invB : 0.f;
                        }
                    }
                }

                // store E (fp32) into QsE region
#pragma unroll
                for (int i = 0; i < 2; i++) {
                    int r0 = wm * 32 + i * 16 + gg;
#pragma unroll
                    for (int j = 0; j < 4; j++) {
                        int cl = wn * 32 + j * 8 + 2 * t4;
                        *(float2*)&QsE[r0 * SQ_ + cl]       = make_float2(s[i][j][0], s[i][j][1]);
                        *(float2*)&QsE[(r0 + 8) * SQ_ + cl] = make_float2(s[i][j][2], s[i][j][3]);
                    }
                }
                __syncthreads();  // E complete

                // coalesced write of NORMALIZED P
                if (writeP) {
                    float* Pd = P + (size_t)bh * S_ * S_ + (size_t)q0 * S_ + k0;
#pragma unroll
                    for (int i = 0; i < 8; i++) {
                        int idx = tid + i * 256;
                        int row = idx >> 4, cc = (idx & 15) * 4;
                        *(float4*)&Pd[(size_t)row * S_ + cc] =
                            *(const float4*)&QsE[row * SQ_ + cc];
                    }
                }

                // O += E_norm @ V
#pragma unroll
                for (int kk = 0; kk < 8; kk++) {
                    uint32_t af[2][4], bf[4][2];
#pragma unroll
                    for (int i = 0; i < 2; i++) {
                        int r0 = wm * 32 + i * 16 + gg;
                        af[i][0] = f2tf(QsE[r0 * SQ_ + kk * 8 + t4]);
                        af[i][1] = f2tf(QsE[(r0 + 8) * SQ_ + kk * 8 + t4]);
                        af[i][2] = f2tf(QsE[r0 * SQ_ + kk * 8 + t4 + 4]);
                        af[i][3] = f2tf(QsE[(r0 + 8) * SQ_ + kk * 8 + t4 + 4]);
                    }
#pragma unroll
                    for (int j = 0; j < 4; j++) {
                        int n0 = wn * 32 + j * 8 + gg;
                        bf[j][0] = __float_as_uint(Vb[(kk * 8 + t4) * SV_ + n0]);
                        bf[j][1] = __float_as_uint(Vb[(kk * 8 + t4 + 4) * SV_ + n0]);
                    }
#pragma unroll
                    for (int i = 0; i < 2; i++)
#pragma unroll
                        for (int j = 0; j < 4; j++)
                            mma8(o[i][j], af[i][0], af[i][1], af[i][2], af[i][3],
                                 bf[j][0], bf[j][1]);
                }
            } else if (writeP) {
                float* Pd = P + (size_t)bh * S_ * S_ + (size_t)q0 * S_ + k0;
                const float4 z = make_float4(0.f, 0.f, 0.f, 0.f);
#pragma unroll
                for (int i = 0; i < 8; i++) {
                    int idx = tid + i * 256;
                    int row = idx >> 4, cc = (idx & 15) * 4;
                    *(float4*)&Pd[(size_t)row * S_ + cc] = z;
                }
            }
        }

        // epilogue: store O as tf32 bits (feeds cvt-free final GEMM)
        const int bb = bh >> 4, hh = bh & 15;
#pragma unroll
        for (int i = 0; i < 2; i++) {
            int r0 = wm * 32 + i * 16 + gg;
            int mA = bb * S_ + q0 + r0;
#pragma unroll
            for (int j = 0; j < 4; j++) {
                int cl = hh * 64 + wn * 32 + j * 8 + 2 * t4;
                *(float2*)&g_ao[(size_t)mA * D_ + cl] =
                    make_float2(__uint_as_float(f2tf(o[i][j][0])),
                                __uint_as_float(f2tf(o[i][j][1])));
                *(float2*)&g_ao[(size_t)(mA + 8) * D_ + cl] =
                    make_float2(__uint_as_float(f2tf(o[i][j][2])),
                                __uint_as_float(f2tf(o[i][j][3])));
            }
        }
    }
}

// ============================================================
extern "C" void kernel_launch(void* const* d_in, const int* in_sizes, int n_in,
                              void* d_out, int out_size)
{
    const float* query = (const float*)d_in[0];
    const float* key_  = (const float*)d_in[1];
    const float* value = (const float*)d_in[2];
    // d_in[3] = causal mask — handled analytically
    const float* Wq = (const float*)d_in[4];
    const float* bq = (const float*)d_in[5];
    const float* Wk = (const float*)d_in[6];
    const float* bk = (const float*)d_in[7];
    const float* Wv = (const float*)d_in[8];
    const float* bv = (const float*)d_in[9];
    const float* Wo = (const float*)d_in[10];
    const float* bo = (const float*)d_in[11];
    float* out = (float*)d_out;

    const long long outN  = (long long)M_ * D_;
    const long long attnN = (long long)BH_ * S_ * S_;

    int hasOut = 1, hasAttn = 0;
    float* Pdst = nullptr;
    if ((long long)out_size >= outN + attnN) { hasAttn = 1; Pdst = out + outN; }
    else if ((long long)out_size == attnN)   { hasOut = 0; hasAttn = 1; Pdst = out; }

    cudaFuncSetAttribute(attn_kernel,
                         cudaFuncAttributeMaxDynamicSharedMemorySize, ATTN_SMEM);
    cudaFuncSetAttribute(gemm_tc_kernel,
                         cudaFuncAttributeMaxDynamicSharedMemorySize, GEMM_SMEM);

    convert_kernel<<<512, 256>>>(
        (const float4*)query, (const float4*)key_, (const float4*)value,
        (const float4*)Wq, (const float4*)Wk, (const float4*)Wv,
        (const float4*)Wo, (const float4*)bq);

    // fused Q/K/V projections: one launch, 768 CTAs
    gemm_tc_kernel<<<dim3(D_ / 128, M_ / 128, 3), 256, GEMM_SMEM>>>(
        bk, bv, nullptr, nullptr, 99);

    attn_kernel<<<dim3(NQT2_ / 2, BH_), 256, ATTN_SMEM>>>(Pdst, hasAttn);

    if (hasOut)
        gemm_tc_kernel<<<dim3(D_ / 128, M_ / 128, 1), 256, GEMM_SMEM>>>(
            nullptr, nullptr, bo, out, 0);
}

// round 10
// speedup vs baseline: 1.8730x; 1.5992x over previous
#include <cuda_runtime.h>
#include <cuda_fp16.h>
#include <cstdint>

// ---------------- problem constants ----------------
static constexpr int B_   = 2;
static constexpr int S_   = 2048;
static constexpr int D_   = 1024;
static constexpr int H_   = 16;
static constexpr int HD_  = 64;
static constexpr int M_   = B_ * S_;    // 4096
static constexpr int BH_  = B_ * H_;    // 32
static constexpr int QT_  = 128;
static constexpr int NQT2_ = S_ / QT_;  // 16
static constexpr float INV_SCALE = 0.125f;  // 1/sqrt(64), exact power of 2

// ---------------- device scratch (fp16) ----------------
__device__ __align__(256) __half g_xq[(size_t)M_ * D_];
__device__ __align__(256) __half g_xk[(size_t)M_ * D_];
__device__ __align__(256) __half g_xv[(size_t)M_ * D_];
__device__ __align__(256) __half g_wq[(size_t)D_ * D_];   // pre-scaled x1/8
__device__ __align__(256) __half g_wk[(size_t)D_ * D_];
__device__ __align__(256) __half g_wv[(size_t)D_ * D_];
__device__ __align__(256) __half g_wo[(size_t)D_ * D_];
__device__ __align__(256) float  g_bqs[D_];               // bq x 1/8 (fp32)
__device__ __align__(256) __half g_q [(size_t)BH_ * S_ * HD_];  // [bh][s][hd], pre-scaled
__device__ __align__(256) __half g_k [(size_t)BH_ * S_ * HD_];  // [bh][s][hd]
__device__ __align__(256) __half g_v [(size_t)BH_ * S_ * HD_];  // TRANSPOSED: [bh][hd][s]
__device__ __align__(256) __half g_ao[(size_t)M_ * D_];

// ---------------- helpers ----------------
__device__ __forceinline__ uint32_t smem_u32(const void* p) {
    uint32_t a;
    asm("{ .reg .u64 t; cvta.to.shared.u64 t, %1; cvt.u32.u64 %0, t; }" : "=r"(a) : "l"(p));
    return a;
}
__device__ __forceinline__ void cp_async16(uint32_t saddr, const void* gaddr) {
    asm volatile("cp.async.cg.shared.global [%0], [%1], 16;" :: "r"(saddr), "l"(gaddr));
}
__device__ __forceinline__ uint32_t f2h2(float x, float y) {
    __half2 h = __floats2half2_rn(x, y);
    return *(uint32_t*)&h;
}
// C += A(16x16 row) * B(16x8 col), fp16 in / fp32 accum
__device__ __forceinline__ void mma16(float* c, uint32_t a0, uint32_t a1, uint32_t a2,
                                      uint32_t a3, uint32_t b0, uint32_t b1) {
    asm volatile(
        "mma.sync.aligned.m16n8k16.row.col.f32.f16.f16.f32 "
        "{%0,%1,%2,%3}, {%4,%5,%6,%7}, {%8,%9}, {%0,%1,%2,%3};"
        : "+f"(c[0]), "+f"(c[1]), "+f"(c[2]), "+f"(c[3])
        : "r"(a0), "r"(a1), "r"(a2), "r"(a3), "r"(b0), "r"(b1));
}
__device__ __forceinline__ uint32_t ldsm32(const __half* p, int idx) {
    return *(const uint32_t*)&p[idx];   // idx must be even
}

// ============================================================
// Pre-conversion: fp32 -> fp16. Wq,bq scaled by 1/8 (exact).
// ============================================================
__global__ __launch_bounds__(256) void convert_kernel(
    const float4* __restrict__ q, const float4* __restrict__ k,
    const float4* __restrict__ v, const float4* __restrict__ wq,
    const float4* __restrict__ wk, const float4* __restrict__ wv,
    const float4* __restrict__ wo, const float4* __restrict__ bq)
{
    constexpr int NQ4 = M_ * D_ / 4;
    constexpr int NW4 = D_ * D_ / 4;
    constexpr int NB4 = D_ / 4;
    constexpr int TOT = 3 * NQ4 + 4 * NW4 + NB4;

    for (int i = blockIdx.x * blockDim.x + threadIdx.x; i < TOT;
         i += gridDim.x * blockDim.x) {
        int j = i;
        const float4* src; __half* dsth = nullptr; float sc = 1.f;
        if (j < NQ4)                    { src = q;  dsth = g_xq; }
        else if ((j -= NQ4) < NQ4)      { src = k;  dsth = g_xk; }
        else if ((j -= NQ4) < NQ4)      { src = v;  dsth = g_xv; }
        else if ((j -= NQ4) < NW4)      { src = wq; dsth = g_wq; sc = INV_SCALE; }
        else if ((j -= NW4) < NW4)      { src = wk; dsth = g_wk; }
        else if ((j -= NW4) < NW4)      { src = wv; dsth = g_wv; }
        else if ((j -= NW4) < NW4)      { src = wo; dsth = g_wo; }
        else {
            j -= NW4;
            float4 s = bq[j];
            ((float4*)g_bqs)[j] = make_float4(s.x * INV_SCALE, s.y * INV_SCALE,
                                              s.z * INV_SCALE, s.w * INV_SCALE);
            continue;
        }
        float4 s = src[j];
        uint2 o = make_uint2(f2h2(s.x * sc, s.y * sc), f2h2(s.z * sc, s.w * sc));
        ((uint2*)dsth)[j] = o;
    }
}

// ============================================================
// fp16 mma GEMM, 3-buffer single-sync pipeline. BK=32 halfs.
//   modeParam==99: fused QKV, mode = blockIdx.z + 1
//   mode 1: g_xq@g_wq+g_bqs -> g_q ; 2: -> g_k ; 3: -> g_v (TRANSPOSED)
//   mode 0: g_ao@g_wo+bo -> out (fp32)
// ============================================================
static constexpr int SAH = 40;                           // halfs per smem row
static constexpr int GEMM_SMEM = 3 * 2 * 128 * SAH * 2;  // 61440 B

__global__ __launch_bounds__(256, 2) void gemm_tc_kernel(
    const float* __restrict__ biasK, const float* __restrict__ biasV,
    const float* __restrict__ biasO, float* __restrict__ outPlain, int modeParam)
{
    extern __shared__ __half smh[];
    // buffer b: A at b*2*128*SAH, B at +128*SAH

    const int mode = (modeParam == 99) ? (int)blockIdx.z + 1 : modeParam;
    const __half* A = (mode == 1) ? g_xq : (mode == 2) ? g_xk
                    : (mode == 3) ? g_xv : g_ao;
    const __half* W = (mode == 1) ? g_wq : (mode == 2) ? g_wk
                    : (mode == 3) ? g_wv : g_wo;
    const float* bias = (mode == 1) ? g_bqs : (mode == 2) ? biasK
                      : (mode == 3) ? biasV : biasO;

    const int tid  = threadIdx.x;
    const int lane = tid & 31;
    const int w    = tid >> 5;
    const int gg   = lane >> 2;
    const int t4   = lane & 3;
    const int wm   = w & 1;
    const int wn   = w >> 1;
    const int rowBase = blockIdx.y * 128;
    const int colBase = blockIdx.x * 128;
    const int K = D_;

    const uint32_t sBase = smem_u32(smh);

    auto stage = [&](int st, int k0) {
#pragma unroll
        for (int ii = 0; ii < 2; ii++) {
            int idx = tid * 2 + ii;          // 0..511
            int row = idx >> 2;              // 0..127
            int ch  = (idx & 3) * 8;         // half offset within BK=32
            uint32_t off = (uint32_t)(st * 2 * 128 * SAH + row * SAH + ch) * 2u;
            cp_async16(sBase + off, &A[(size_t)(rowBase + row) * K + k0 + ch]);
            cp_async16(sBase + off + 128 * SAH * 2, &W[(size_t)(colBase + row) * K + k0 + ch]);
        }
        asm volatile("cp.async.commit_group;" ::: "memory");
    };

    float c[4][4][4];
#pragma unroll
    for (int i = 0; i < 4; i++)
#pragma unroll
        for (int j = 0; j < 4; j++)
#pragma unroll
            for (int q = 0; q < 4; q++) c[i][j][q] = 0.f;

    const int NCH = K / 32;  // 32 stages
    stage(0, 0);
    stage(1, 32);

    for (int ch = 0; ch < NCH; ch++) {
        if (ch < NCH - 1) asm volatile("cp.async.wait_group 1;" ::: "memory");
        else              asm volatile("cp.async.wait_group 0;" ::: "memory");
        __syncthreads();
        if (ch + 2 < NCH) stage((ch + 2) % 3, (ch + 2) * 32);

        const __half* Ab = smh + (ch % 3) * 2 * 128 * SAH;
        const __half* Bb = Ab + 128 * SAH;
#pragma unroll
        for (int kk = 0; kk < 32; kk += 16) {
            uint32_t af[4][4], bf[4][2];
#pragma unroll
            for (int i = 0; i < 4; i++) {
                int r0 = wm * 64 + i * 16 + gg;
                af[i][0] = ldsm32(Ab, r0 * SAH + kk + 2 * t4);
                af[i][1] = ldsm32(Ab, (r0 + 8) * SAH + kk + 2 * t4);
                af[i][2] = ldsm32(Ab, r0 * SAH + kk + 8 + 2 * t4);
                af[i][3] = ldsm32(Ab, (r0 + 8) * SAH + kk + 8 + 2 * t4);
            }
#pragma unroll
            for (int j = 0; j < 4; j++) {
                int n0 = wn * 32 + j * 8 + gg;
                bf[j][0] = ldsm32(Bb, n0 * SAH + kk + 2 * t4);
                bf[j][1] = ldsm32(Bb, n0 * SAH + kk + 8 + 2 * t4);
            }
#pragma unroll
            for (int i = 0; i < 4; i++)
#pragma unroll
                for (int j = 0; j < 4; j++)
                    mma16(c[i][j], af[i][0], af[i][1], af[i][2], af[i][3],
                          bf[j][0], bf[j][1]);
        }
    }

#pragma unroll
    for (int i = 0; i < 4; i++) {
#pragma unroll
        for (int j = 0; j < 4; j++) {
            int r0  = rowBase + wm * 64 + i * 16 + gg;
            int col = colBase + wn * 32 + j * 8 + 2 * t4;
            float2 b2 = *(const float2*)&bias[col];
#pragma unroll
            for (int h = 0; h < 2; h++) {
                int m = r0 + h * 8;
                float x = c[i][j][h * 2 + 0] + b2.x;
                float y = c[i][j][h * 2 + 1] + b2.y;
                if (mode == 0) {
                    *(float2*)&outPlain[(size_t)m * D_ + col] = make_float2(x, y);
                } else {
                    int bb = m >> 11, ss = m & (S_ - 1);
                    int hh = col >> 6, hd = col & 63;
                    if (mode == 3) {
                        // transposed: [bh][hd][s]
                        __half* gv = g_v + (size_t)(bb * H_ + hh) * HD_ * S_;
                        gv[(size_t)hd * S_ + ss]       = __float2half_rn(x);
                        gv[(size_t)(hd + 1) * S_ + ss] = __float2half_rn(y);
                    } else {
                        __half* tgt = (mode == 1) ? g_q : g_k;
                        *(uint32_t*)&tgt[(((size_t)(bb * H_ + hh)) * S_ + ss) * HD_ + hd] =
                            f2h2(x, y);
                    }
                }
            }
        }
    }
}

// ============================================================
// Fused causal attention (fp16 MMA), two sweeps, paired q-tiles,
// double-buffered K (sweep1) and K+V (sweep2).
// Smem: E32 f32[128][68] (Q fp16 staging aliases) | Eh h[128][72]
//       | Kdb h 2x[64][72] | Vdb h 2x[64][72] (Vt: [hd][seq]) | inv_s f[128]
// ============================================================
static constexpr int SQ_  = 68;   // E32 float stride
static constexpr int SH_  = 72;   // half-row stride
static constexpr int OFF_EH  = 128 * SQ_ * 4;            // 34816
static constexpr int OFF_K   = OFF_EH + 128 * SH_ * 2;   // 53248
static constexpr int OFF_V   = OFF_K + 2 * 64 * SH_ * 2; // 71680
static constexpr int OFF_INV = OFF_V + 2 * 64 * SH_ * 2; // 90112
static constexpr int ATTN_SMEM = OFF_INV + 128 * 4;      // 90624 B

__global__ __launch_bounds__(256, 2) void attn_kernel(float* __restrict__ P, int writeP)
{
    extern __shared__ char smc[];
    float*  E32   = (float*)smc;
    __half* Qh    = (__half*)smc;            // aliases E32 during Q staging
    __half* Eh    = (__half*)(smc + OFF_EH);
    __half* Kdb   = (__half*)(smc + OFF_K);
    __half* Vdb   = (__half*)(smc + OFF_V);
    float*  inv_s = (float*)(smc + OFF_INV);
    float*  rsc   = (float*)Vdb;             // rowsum scratch (256 floats)

    const int tid  = threadIdx.x;
    const int lane = tid & 31;
    const int w    = tid >> 5;
    const int gg   = lane >> 2;
    const int t4   = lane & 3;
    const int wm   = w & 3;
    const int wn   = w >> 2;
    const int bh   = blockIdx.y;

    const __half* Qg = g_q + (size_t)bh * S_ * HD_;
    const __half* Kg = g_k + (size_t)bh * S_ * HD_;
    const __half* Vg = g_v + (size_t)bh * S_ * HD_;   // [hd][s]

    const uint32_t sQ = smem_u32(Qh);
    const uint32_t sK = smem_u32(Kdb);
    const uint32_t sV = smem_u32(Vdb);

    auto stageK = [&](int b, int k0) {
#pragma unroll
        for (int i = 0; i < 2; i++) {
            int idx = tid + i * 256;          // 0..511
            int row = idx >> 3, c = (idx & 7) * 8;
            cp_async16(sK + (uint32_t)(b * 64 * SH_ + row * SH_ + c) * 2u,
                       &Kg[(size_t)(k0 + row) * HD_ + c]);
        }
    };
    auto stageV = [&](int b, int k0) {        // Vt rows = hd, cols = seq
#pragma unroll
        for (int i = 0; i < 2; i++) {
            int idx = tid + i * 256;
            int row = idx >> 3, c = (idx & 7) * 8;
            cp_async16(sV + (uint32_t)(b * 64 * SH_ + row * SH_ + c) * 2u,
                       &Vg[(size_t)row * S_ + k0 + c]);
        }
    };

#pragma unroll 1
    for (int p = 0; p < 2; p++) {
        const int qt = p == 0 ? (NQT2_ - 1) - (int)blockIdx.x : (int)blockIdx.x;
        const int q0 = qt * QT_;
        __syncthreads();  // previous pair fully done

        // stage Q tile (fp16, pre-scaled): 128 rows x 64 halfs
#pragma unroll
        for (int i = 0; i < 4; i++) {
            int idx = tid + i * 256;          // 0..1023
            int row = idx >> 3, c = (idx & 7) * 8;
            cp_async16(sQ + (uint32_t)(row * SH_ + c) * 2u,
                       &Qg[(size_t)(q0 + row) * HD_ + c]);
        }
        asm volatile("cp.async.commit_group;" ::: "memory");
        asm volatile("cp.async.wait_group 0;" ::: "memory");
        __syncthreads();

        // Q fragments -> registers: 4 k16-chunks x 8 regs
        uint32_t qf[4][8];
#pragma unroll
        for (int ck = 0; ck < 4; ck++) {
#pragma unroll
            for (int i = 0; i < 2; i++) {
                int r0 = wm * 32 + i * 16 + gg;
                qf[ck][i * 4 + 0] = ldsm32(Qh, r0 * SH_ + ck * 16 + 2 * t4);
                qf[ck][i * 4 + 1] = ldsm32(Qh, (r0 + 8) * SH_ + ck * 16 + 2 * t4);
                qf[ck][i * 4 + 2] = ldsm32(Qh, r0 * SH_ + ck * 16 + 8 + 2 * t4);
                qf[ck][i * 4 + 3] = ldsm32(Qh, (r0 + 8) * SH_ + ck * 16 + 8 + 2 * t4);
            }
        }
        __syncthreads();  // Q region now free (E32 aliases it)

        const int nkt = 2 * qt + 2;

        // ================= sweep 1: rowsums =================
        stageK(0, 0);
        asm volatile("cp.async.commit_group;" ::: "memory");

        float rs[2][2] = {{0.f, 0.f}, {0.f, 0.f}};
        for (int kt = 0; kt < nkt; kt++) {
            const int b = kt & 1;
            __syncthreads();
            if (kt + 1 < nkt) {
                stageK(1 - b, (kt + 1) * 64);
                asm volatile("cp.async.commit_group;" ::: "memory");
                asm volatile("cp.async.wait_group 1;" ::: "memory");
            } else {
                asm volatile("cp.async.wait_group 0;" ::: "memory");
            }
            __syncthreads();

            const __half* Kb = Kdb + b * 64 * SH_;
            float s[2][4][4];
#pragma unroll
            for (int i = 0; i < 2; i++)
#pragma unroll
                for (int j = 0; j < 4; j++)
#pragma unroll
                    for (int q = 0; q < 4; q++) s[i][j][q] = 0.f;
#pragma unroll
            for (int ck = 0; ck < 4; ck++) {
                uint32_t bf[4][2];
#pragma unroll
                for (int j = 0; j < 4; j++) {
                    int n0 = wn * 32 + j * 8 + gg;
                    bf[j][0] = ldsm32(Kb, n0 * SH_ + ck * 16 + 2 * t4);
                    bf[j][1] = ldsm32(Kb, n0 * SH_ + ck * 16 + 8 + 2 * t4);
                }
#pragma unroll
                for (int i = 0; i < 2; i++)
#pragma unroll
                    for (int j = 0; j < 4; j++)
                        mma16(s[i][j], qf[ck][i * 4 + 0], qf[ck][i * 4 + 1],
                              qf[ck][i * 4 + 2], qf[ck][i * 4 + 3], bf[j][0], bf[j][1]);
            }

            const int k0 = kt * 64;
            if (k0 + 63 <= q0 + wm * 32) {
#pragma unroll
                for (int i = 0; i < 2; i++)
#pragma unroll
                    for (int j = 0; j < 4; j++) {
                        rs[i][0] += __expf(s[i][j][0]) + __expf(s[i][j][1]);
                        rs[i][1] += __expf(s[i][j][2]) + __expf(s[i][j][3]);
                    }
            } else {
#pragma unroll
                for (int i = 0; i < 2; i++) {
                    int qiA = q0 + wm * 32 + i * 16 + gg, qiB = qiA + 8;
#pragma unroll
                    for (int j = 0; j < 4; j++) {
                        int ki0 = k0 + wn * 32 + j * 8 + 2 * t4, ki1 = ki0 + 1;
                        rs[i][0] += ((ki0 <= qiA) ? __expf(s[i][j][0]) : 0.f)
                                  + ((ki1 <= qiA) ? __expf(s[i][j][1]) : 0.f);
                        rs[i][1] += ((ki0 <= qiB) ? __expf(s[i][j][2]) : 0.f)
                                  + ((ki1 <= qiB) ? __expf(s[i][j][3]) : 0.f);
                    }
                }
            }
        }
#pragma unroll
        for (int i = 0; i < 2; i++) {
#pragma unroll
            for (int h = 0; h < 2; h++) {
                rs[i][h] += __shfl_xor_sync(0xFFFFFFFF, rs[i][h], 1);
                rs[i][h] += __shfl_xor_sync(0xFFFFFFFF, rs[i][h], 2);
            }
        }
        __syncthreads();
        if (t4 == 0) {
#pragma unroll
            for (int i = 0; i < 2; i++) {
                int r0 = wm * 32 + i * 16 + gg;
                rsc[wn * 128 + r0]     = rs[i][0];
                rsc[wn * 128 + r0 + 8] = rs[i][1];
            }
        }
        __syncthreads();
        if (tid < 128) inv_s[tid] = 1.f / (rsc[tid] + rsc[128 + tid]);
        __syncthreads();

        // ================= sweep 2: P + O =================
        float o[2][4][4];
#pragma unroll
        for (int i = 0; i < 2; i++)
#pragma unroll
            for (int j = 0; j < 4; j++)
#pragma unroll
                for (int q = 0; q < 4; q++) o[i][j][q] = 0.f;

        stageK(0, 0); stageV(0, 0);
        asm volatile("cp.async.commit_group;" ::: "memory");

        for (int kt = 0; kt < S_ / 64; kt++) {
            const int k0 = kt * 64;
            if (kt < nkt) {
                const int b = kt & 1;
                __syncthreads();
                if (kt + 1 < nkt) {
                    stageK(1 - b, (kt + 1) * 64);
                    stageV(1 - b, (kt + 1) * 64);
                    asm volatile("cp.async.commit_group;" ::: "memory");
                    asm volatile("cp.async.wait_group 1;" ::: "memory");
                } else {
                    asm volatile("cp.async.wait_group 0;" ::: "memory");
                }
                __syncthreads();

                const __half* Kb = Kdb + b * 64 * SH_;
                const __half* Vb = Vdb + b * 64 * SH_;

                float s[2][4][4];
#pragma unroll
                for (int i = 0; i < 2; i++)
#pragma unroll
                    for (int j = 0; j < 4; j++)
#pragma unroll
                        for (int q = 0; q < 4; q++) s[i][j][q] = 0.f;
#pragma unroll
                for (int ck = 0; ck < 4; ck++) {
                    uint32_t bf[4][2];
#pragma unroll
                    for (int j = 0; j < 4; j++) {
                        int n0 = wn * 32 + j * 8 + gg;
                        bf[j][0] = ldsm32(Kb, n0 * SH_ + ck * 16 + 2 * t4);
                        bf[j][1] = ldsm32(Kb, n0 * SH_ + ck * 16 + 8 + 2 * t4);
                    }
#pragma unroll
                    for (int i = 0; i < 2; i++)
#pragma unroll
                        for (int j = 0; j < 4; j++)
                            mma16(s[i][j], qf[ck][i * 4 + 0], qf[ck][i * 4 + 1],
                                  qf[ck][i * 4 + 2], qf[ck][i * 4 + 3],
                                  bf[j][0], bf[j][1]);
                }

                // e_norm = exp * inv, masked only on edge tiles
#pragma unroll
                for (int i = 0; i < 2; i++) {
                    int r0 = wm * 32 + i * 16 + gg;
                    float invA = inv_s[r0], invB = inv_s[r0 + 8];
                    if (k0 + 63 <= q0 + wm * 32) {
#pragma unroll
                        for (int j = 0; j < 4; j++) {
                            s[i][j][0] = __expf(s[i][j][0]) * invA;
                            s[i][j][1] = __expf(s[i][j][1]) * invA;
                            s[i][j][2] = __expf(s[i][j][2]) * invB;
                            s[i][j][3] = __expf(s[i][j][3]) * invB;
                        }
                    } else {
                        int qiA = q0 + r0, qiB = qiA + 8;
#pragma unroll
                        for (int j = 0; j < 4; j++) {
                            int ki0 = k0 + wn * 32 + j * 8 + 2 * t4, ki1 = ki0 + 1;
                            s[i][j][0] = (ki0 <= qiA) ? __expf(s[i][j][0]) * invA : 0.f;
                            s[i][j][1] = (ki1 <= qiA) ? __expf(s[i][j][1]) * invA : 0.f;
                            s[i][j][2] = (ki0 <= qiB) ? __expf(s[i][j][2]) * invB : 0.f;
                            s[i][j][3] = (ki1 <= qiB) ? __expf(s[i][j][3]) * invB : 0.f;
                        }
                    }
                }

                // dual-store E: fp16 for MMA, fp32 for P write
#pragma unroll
                for (int i = 0; i < 2; i++) {
                    int r0 = wm * 32 + i * 16 + gg;
#pragma unroll
                    for (int j = 0; j < 4; j++) {
                        int cl = wn * 32 + j * 8 + 2 * t4;
                        *(uint32_t*)&Eh[r0 * SH_ + cl]       = f2h2(s[i][j][0], s[i][j][1]);
                        *(uint32_t*)&Eh[(r0 + 8) * SH_ + cl] = f2h2(s[i][j][2], s[i][j][3]);
                        if (writeP) {
                            *(float2*)&E32[r0 * SQ_ + cl] =
                                make_float2(s[i][j][0], s[i][j][1]);
                            *(float2*)&E32[(r0 + 8) * SQ_ + cl] =
                                make_float2(s[i][j][2], s[i][j][3]);
                        }
                    }
                }
                __syncthreads();

                // coalesced write of NORMALIZED P
                if (writeP) {
                    float* Pd = P + (size_t)bh * S_ * S_ + (size_t)q0 * S_ + k0;
#pragma unroll
                    for (int i = 0; i < 8; i++) {
                        int idx = tid + i * 256;
                        int row = idx >> 4, cc = (idx & 15) * 4;
                        *(float4*)&Pd[(size_t)row * S_ + cc] =
                            *(const float4*)&E32[row * SQ_ + cc];
                    }
                }

                // O += E_norm @ V   (B operand from transposed V tile)
#pragma unroll
                for (int ck = 0; ck < 4; ck++) {
                    uint32_t af[2][4], bf[4][2];
#pragma unroll
                    for (int i = 0; i < 2; i++) {
                        int r0 = wm * 32 + i * 16 + gg;
                        af[i][0] = ldsm32(Eh, r0 * SH_ + ck * 16 + 2 * t4);
                        af[i][1] = ldsm32(Eh, (r0 + 8) * SH_ + ck * 16 + 2 * t4);
                        af[i][2] = ldsm32(Eh, r0 * SH_ + ck * 16 + 8 + 2 * t4);
                        af[i][3] = ldsm32(Eh, (r0 + 8) * SH_ + ck * 16 + 8 + 2 * t4);
                    }
#pragma unroll
                    for (int j = 0; j < 4; j++) {
                        int n0 = wn * 32 + j * 8 + gg;     // hd index (Vt rows)
                        bf[j][0] = ldsm32(Vb, n0 * SH_ + ck * 16 + 2 * t4);
                        bf[j][1] = ldsm32(Vb, n0 * SH_ + ck * 16 + 8 + 2 * t4);
                    }
#pragma unroll
                    for (int i = 0; i < 2; i++)
#pragma unroll
                        for (int j = 0; j < 4; j++)
                            mma16(o[i][j], af[i][0], af[i][1], af[i][2], af[i][3],
                                  bf[j][0], bf[j][1]);
                }
            } else if (writeP) {
                float* Pd = P + (size_t)bh * S_ * S_ + (size_t)q0 * S_ + k0;
                const float4 z = make_float4(0.f, 0.f, 0.f, 0.f);
#pragma unroll
                for (int i = 0; i < 8; i++) {
                    int idx = tid + i * 256;
                    int row = idx >> 4, cc = (idx & 15) * 4;
                    *(float4*)&Pd[(size_t)row * S_ + cc] = z;
                }
            }
        }

        // epilogue: O -> g_ao (fp16)
        const int bb = bh >> 4, hh = bh & 15;
#pragma unroll
        for (int i = 0; i < 2; i++) {
            int r0 = wm * 32 + i * 16 + gg;
            int mA = bb * S_ + q0 + r0;
#pragma unroll
            for (int j = 0; j < 4; j++) {
                int cl = hh * 64 + wn * 32 + j * 8 + 2 * t4;
                *(uint32_t*)&g_ao[(size_t)mA * D_ + cl]       = f2h2(o[i][j][0], o[i][j][1]);
                *(uint32_t*)&g_ao[(size_t)(mA + 8) * D_ + cl] = f2h2(o[i][j][2], o[i][j][3]);
            }
        }
    }
}

// ============================================================
extern "C" void kernel_launch(void* const* d_in, const int* in_sizes, int n_in,
                              void* d_out, int out_size)
{
    const float* query = (const float*)d_in[0];
    const float* key_  = (const float*)d_in[1];
    const float* value = (const float*)d_in[2];
    // d_in[3] = causal mask — handled analytically
    const float* Wq = (const float*)d_in[4];
    const float* bq = (const float*)d_in[5];
    const float* Wk = (const float*)d_in[6];
    const float* bk = (const float*)d_in[7];
    const float* Wv = (const float*)d_in[8];
    const float* bv = (const float*)d_in[9];
    const float* Wo = (const float*)d_in[10];
    const float* bo = (const float*)d_in[11];
    float* out = (float*)d_out;

    const long long outN  = (long long)M_ * D_;
    const long long attnN = (long long)BH_ * S_ * S_;

    int hasOut = 1, hasAttn = 0;
    float* Pdst = nullptr;
    if ((long long)out_size >= outN + attnN) { hasAttn = 1; Pdst = out + outN; }
    else if ((long long)out_size == attnN)   { hasOut = 0; hasAttn = 1; Pdst = out; }

    cudaFuncSetAttribute(attn_kernel,
                         cudaFuncAttributeMaxDynamicSharedMemorySize, ATTN_SMEM);
    cudaFuncSetAttribute(gemm_tc_kernel,
                         cudaFuncAttributeMaxDynamicSharedMemorySize, GEMM_SMEM);

    convert_kernel<<<512, 256>>>(
        (const float4*)query, (const float4*)key_, (const float4*)value,
        (const float4*)Wq, (const float4*)Wk, (const float4*)Wv,
        (const float4*)Wo, (const float4*)bq);

    // fused Q/K/V projections
    gemm_tc_kernel<<<dim3(D_ / 128, M_ / 128, 3), 256, GEMM_SMEM>>>(
        bk, bv, nullptr, nullptr, 99);

    attn_kernel<<<dim3(NQT2_ / 2, BH_), 256, ATTN_SMEM>>>(Pdst, hasAttn);

    if (hasOut)
        gemm_tc_kernel<<<dim3(D_ / 128, M_ / 128, 1), 256, GEMM_SMEM>>>(
            nullptr, nullptr, bo, out, 0);
}

// round 11
// speedup vs baseline: 1.8779x; 1.0026x over previous
#include <cuda_runtime.h>
#include <cuda_fp16.h>
#include <cstdint>

// ---------------- problem constants ----------------
static constexpr int B_   = 2;
static constexpr int S_   = 2048;
static constexpr int D_   = 1024;
static constexpr int H_   = 16;
static constexpr int HD_  = 64;
static constexpr int M_   = B_ * S_;    // 4096
static constexpr int BH_  = B_ * H_;    // 32
static constexpr int QT_  = 128;
static constexpr int NQT2_ = S_ / QT_;  // 16
static constexpr float INV_SCALE = 0.125f;  // 1/sqrt(64), exact power of 2

// ---------------- device scratch (fp16) ----------------
__device__ __align__(256) __half g_xq[(size_t)M_ * D_];
__device__ __align__(256) __half g_xk[(size_t)M_ * D_];
__device__ __align__(256) __half g_xv[(size_t)M_ * D_];
__device__ __align__(256) __half g_wq[(size_t)D_ * D_];   // pre-scaled x1/8
__device__ __align__(256) __half g_wk[(size_t)D_ * D_];
__device__ __align__(256) __half g_wv[(size_t)D_ * D_];
__device__ __align__(256) __half g_wo[(size_t)D_ * D_];
__device__ __align__(256) float  g_bqs[D_];               // bq x 1/8 (fp32)
__device__ __align__(256) __half g_q [(size_t)BH_ * S_ * HD_];  // [bh][s][hd], pre-scaled
__device__ __align__(256) __half g_k [(size_t)BH_ * S_ * HD_];  // [bh][s][hd]
__device__ __align__(256) __half g_v [(size_t)BH_ * S_ * HD_];  // TRANSPOSED: [bh][hd][s]
__device__ __align__(256) __half g_ao[(size_t)M_ * D_];

// ---------------- helpers ----------------
__device__ __forceinline__ uint32_t smem_u32(const void* p) {
    uint32_t a;
    asm("{ .reg .u64 t; cvta.to.shared.u64 t, %1; cvt.u32.u64 %0, t; }" : "=r"(a) : "l"(p));
    return a;
}
__device__ __forceinline__ void cp_async16(uint32_t saddr, const void* gaddr) {
    asm volatile("cp.async.cg.shared.global [%0], [%1], 16;" :: "r"(saddr), "l"(gaddr));
}
__device__ __forceinline__ uint32_t f2h2(float x, float y) {
    __half2 h = __floats2half2_rn(x, y);
    return *(uint32_t*)&h;
}
__device__ __forceinline__ void mma16(float* c, uint32_t a0, uint32_t a1, uint32_t a2,
                                      uint32_t a3, uint32_t b0, uint32_t b1) {
    asm volatile(
        "mma.sync.aligned.m16n8k16.row.col.f32.f16.f16.f32 "
        "{%0,%1,%2,%3}, {%4,%5,%6,%7}, {%8,%9}, {%0,%1,%2,%3};"
        : "+f"(c[0]), "+f"(c[1]), "+f"(c[2]), "+f"(c[3])
        : "r"(a0), "r"(a1), "r"(a2), "r"(a3), "r"(b0), "r"(b1));
}
// ldmatrix x4: loads 4 8x8 b16 matrices; lane groups 0-7/8-15/16-23/24-31
// provide rows (r..r+7,kk) / (r+8..r+15,kk) / (r..r+7,kk+8) / (r+8..15,kk+8)
__device__ __forceinline__ void ldsm4(uint32_t addr, uint32_t& r0, uint32_t& r1,
                                      uint32_t& r2, uint32_t& r3) {
    asm volatile("ldmatrix.sync.aligned.m8n8.x4.shared.b16 {%0,%1,%2,%3}, [%4];"
                 : "=r"(r0), "=r"(r1), "=r"(r2), "=r"(r3) : "r"(addr));
}
// per-lane ldmatrix address for a 16x16 block at (rowBase, colBase), row stride (halfs)
__device__ __forceinline__ uint32_t lm_addr(uint32_t smemBase, int lane,
                                            int rowBase, int colBase, int strideH) {
    int lr  = lane & 7;
    int r8  = (lane >> 3) & 1;
    int c8  = lane >> 4;
    return smemBase + (uint32_t)((rowBase + lr + r8 * 8) * strideH
                                 + colBase + c8 * 8) * 2u;
}
__device__ __forceinline__ uint32_t ldsm32(const __half* p, int idx) {
    return *(const uint32_t*)&p[idx];
}

// ============================================================
// Pre-conversion: fp32 -> fp16. Wq,bq scaled by 1/8 (exact).
// ============================================================
__global__ __launch_bounds__(256) void convert_kernel(
    const float4* __restrict__ q, const float4* __restrict__ k,
    const float4* __restrict__ v, const float4* __restrict__ wq,
    const float4* __restrict__ wk, const float4* __restrict__ wv,
    const float4* __restrict__ wo, const float4* __restrict__ bq)
{
    constexpr int NQ4 = M_ * D_ / 4;
    constexpr int NW4 = D_ * D_ / 4;
    constexpr int NB4 = D_ / 4;
    constexpr int TOT = 3 * NQ4 + 4 * NW4 + NB4;

    for (int i = blockIdx.x * blockDim.x + threadIdx.x; i < TOT;
         i += gridDim.x * blockDim.x) {
        int j = i;
        const float4* src; __half* dsth = nullptr; float sc = 1.f;
        if (j < NQ4)                    { src = q;  dsth = g_xq; }
        else if ((j -= NQ4) < NQ4)      { src = k;  dsth = g_xk; }
        else if ((j -= NQ4) < NQ4)      { src = v;  dsth = g_xv; }
        else if ((j -= NQ4) < NW4)      { src = wq; dsth = g_wq; sc = INV_SCALE; }
        else if ((j -= NW4) < NW4)      { src = wk; dsth = g_wk; }
        else if ((j -= NW4) < NW4)      { src = wv; dsth = g_wv; }
        else if ((j -= NW4) < NW4)      { src = wo; dsth = g_wo; }
        else {
            j -= NW4;
            float4 s = bq[j];
            ((float4*)g_bqs)[j] = make_float4(s.x * INV_SCALE, s.y * INV_SCALE,
                                              s.z * INV_SCALE, s.w * INV_SCALE);
            continue;
        }
        float4 s = src[j];
        uint2 o = make_uint2(f2h2(s.x * sc, s.y * sc), f2h2(s.z * sc, s.w * sc));
        ((uint2*)dsth)[j] = o;
    }
}

// ============================================================
// fp16 mma GEMM, 3-buffer single-sync pipeline, ldmatrix frags.
// ============================================================
static constexpr int SAH = 40;                           // halfs per smem row (80B: LDSM conflict-free)
static constexpr int GEMM_SMEM = 3 * 2 * 128 * SAH * 2;  // 61440 B

__global__ __launch_bounds__(256, 2) void gemm_tc_kernel(
    const float* __restrict__ biasK, const float* __restrict__ biasV,
    const float* __restrict__ biasO, float* __restrict__ outPlain, int modeParam)
{
    extern __shared__ __half smh[];

    const int mode = (modeParam == 99) ? (int)blockIdx.z + 1 : modeParam;
    const __half* A = (mode == 1) ? g_xq : (mode == 2) ? g_xk
                    : (mode == 3) ? g_xv : g_ao;
    const __half* W = (mode == 1) ? g_wq : (mode == 2) ? g_wk
                    : (mode == 3) ? g_wv : g_wo;
    const float* bias = (mode == 1) ? g_bqs : (mode == 2) ? biasK
                      : (mode == 3) ? biasV : biasO;

    const int tid  = threadIdx.x;
    const int lane = tid & 31;
    const int w    = tid >> 5;
    const int gg   = lane >> 2;
    const int t4   = lane & 3;
    const int wm   = w & 1;
    const int wn   = w >> 1;
    const int rowBase = blockIdx.y * 128;
    const int colBase = blockIdx.x * 128;
    const int K = D_;

    const uint32_t sBase = smem_u32(smh);

    auto stage = [&](int st, int k0) {
#pragma unroll
        for (int ii = 0; ii < 2; ii++) {
            int idx = tid * 2 + ii;
            int row = idx >> 2;
            int ch  = (idx & 3) * 8;
            uint32_t off = (uint32_t)(st * 2 * 128 * SAH + row * SAH + ch) * 2u;
            cp_async16(sBase + off, &A[(size_t)(rowBase + row) * K + k0 + ch]);
            cp_async16(sBase + off + 128 * SAH * 2, &W[(size_t)(colBase + row) * K + k0 + ch]);
        }
        asm volatile("cp.async.commit_group;" ::: "memory");
    };

    float c[4][4][4];
#pragma unroll
    for (int i = 0; i < 4; i++)
#pragma unroll
        for (int j = 0; j < 4; j++)
#pragma unroll
            for (int q = 0; q < 4; q++) c[i][j][q] = 0.f;

    const int NCH = K / 32;
    stage(0, 0);
    stage(1, 32);

    for (int ch = 0; ch < NCH; ch++) {
        if (ch < NCH - 1) asm volatile("cp.async.wait_group 1;" ::: "memory");
        else              asm volatile("cp.async.wait_group 0;" ::: "memory");
        __syncthreads();
        if (ch + 2 < NCH) stage((ch + 2) % 3, (ch + 2) * 32);

        const uint32_t aB = sBase + (uint32_t)((ch % 3) * 2 * 128 * SAH) * 2u;
        const uint32_t bB = aB + 128 * SAH * 2;
#pragma unroll
        for (int kk = 0; kk < 32; kk += 16) {
            uint32_t af[4][4], bf[4][2];
#pragma unroll
            for (int i = 0; i < 4; i++)
                ldsm4(lm_addr(aB, lane, wm * 64 + i * 16, kk, SAH),
                      af[i][0], af[i][1], af[i][2], af[i][3]);
            // one x4 covers two adjacent n-blocks: {b[j][0], b[j+1][0], b[j][1], b[j+1][1]}
#pragma unroll
            for (int jp = 0; jp < 2; jp++)
                ldsm4(lm_addr(bB, lane, wn * 32 + jp * 16, kk, SAH),
                      bf[jp * 2][0], bf[jp * 2 + 1][0], bf[jp * 2][1], bf[jp * 2 + 1][1]);
#pragma unroll
            for (int i = 0; i < 4; i++)
#pragma unroll
                for (int j = 0; j < 4; j++)
                    mma16(c[i][j], af[i][0], af[i][1], af[i][2], af[i][3],
                          bf[j][0], bf[j][1]);
        }
    }

#pragma unroll
    for (int i = 0; i < 4; i++) {
#pragma unroll
        for (int j = 0; j < 4; j++) {
            int r0  = rowBase + wm * 64 + i * 16 + gg;
            int col = colBase + wn * 32 + j * 8 + 2 * t4;
            float2 b2 = *(const float2*)&bias[col];
#pragma unroll
            for (int h = 0; h < 2; h++) {
                int m = r0 + h * 8;
                float x = c[i][j][h * 2 + 0] + b2.x;
                float y = c[i][j][h * 2 + 1] + b2.y;
                if (mode == 0) {
                    *(float2*)&outPlain[(size_t)m * D_ + col] = make_float2(x, y);
                } else {
                    int bb = m >> 11, ss = m & (S_ - 1);
                    int hh = col >> 6, hd = col & 63;
                    if (mode == 3) {
                        __half* gv = g_v + (size_t)(bb * H_ + hh) * HD_ * S_;
                        gv[(size_t)hd * S_ + ss]       = __float2half_rn(x);
                        gv[(size_t)(hd + 1) * S_ + ss] = __float2half_rn(y);
                    } else {
                        __half* tgt = (mode == 1) ? g_q : g_k;
                        *(uint32_t*)&tgt[(((size_t)(bb * H_ + hh)) * S_ + ss) * HD_ + hd] =
                            f2h2(x, y);
                    }
                }
            }
        }
    }
}

// ============================================================
// Fused causal attention (fp16 MMA + ldmatrix), two sweeps,
// paired q-tiles, double-buffered K / K+V.
// ============================================================
static constexpr int SQ_  = 68;   // E32 float stride
static constexpr int SH_  = 72;   // half-row stride (144B: LDSM conflict-free)
static constexpr int OFF_EH  = 128 * SQ_ * 4;            // 34816
static constexpr int OFF_K   = OFF_EH + 128 * SH_ * 2;   // 53248
static constexpr int OFF_V   = OFF_K + 2 * 64 * SH_ * 2; // 71680
static constexpr int OFF_INV = OFF_V + 2 * 64 * SH_ * 2; // 90112
static constexpr int ATTN_SMEM = OFF_INV + 128 * 4;      // 90624 B

__global__ __launch_bounds__(256, 2) void attn_kernel(float* __restrict__ P, int writeP)
{
    extern __shared__ char smc[];
    float*  E32   = (float*)smc;
    __half* Qh    = (__half*)smc;
    __half* Eh    = (__half*)(smc + OFF_EH);
    __half* Kdb   = (__half*)(smc + OFF_K);
    __half* Vdb   = (__half*)(smc + OFF_V);
    float*  inv_s = (float*)(smc + OFF_INV);
    float*  rsc   = (float*)Vdb;

    const int tid  = threadIdx.x;
    const int lane = tid & 31;
    const int w    = tid >> 5;
    const int gg   = lane >> 2;
    const int t4   = lane & 3;
    const int wm   = w & 3;
    const int wn   = w >> 2;
    const int bh   = blockIdx.y;

    const __half* Qg = g_q + (size_t)bh * S_ * HD_;
    const __half* Kg = g_k + (size_t)bh * S_ * HD_;
    const __half* Vg = g_v + (size_t)bh * S_ * HD_;   // [hd][s]

    const uint32_t sQ = smem_u32(Qh);
    const uint32_t sE = smem_u32(Eh);
    const uint32_t sK = smem_u32(Kdb);
    const uint32_t sV = smem_u32(Vdb);

    auto stageK = [&](int b, int k0) {
#pragma unroll
        for (int i = 0; i < 2; i++) {
            int idx = tid + i * 256;
            int row = idx >> 3, c = (idx & 7) * 8;
            cp_async16(sK + (uint32_t)(b * 64 * SH_ + row * SH_ + c) * 2u,
                       &Kg[(size_t)(k0 + row) * HD_ + c]);
        }
    };
    auto stageV = [&](int b, int k0) {
#pragma unroll
        for (int i = 0; i < 2; i++) {
            int idx = tid + i * 256;
            int row = idx >> 3, c = (idx & 7) * 8;
            cp_async16(sV + (uint32_t)(b * 64 * SH_ + row * SH_ + c) * 2u,
                       &Vg[(size_t)row * S_ + k0 + c]);
        }
    };

#pragma unroll 1
    for (int p = 0; p < 2; p++) {
        const int qt = p == 0 ? (NQT2_ - 1) - (int)blockIdx.x : (int)blockIdx.x;
        const int q0 = qt * QT_;
        __syncthreads();

        // stage Q tile (fp16, pre-scaled)
#pragma unroll
        for (int i = 0; i < 4; i++) {
            int idx = tid + i * 256;
            int row = idx >> 3, c = (idx & 7) * 8;
            cp_async16(sQ + (uint32_t)(row * SH_ + c) * 2u,
                       &Qg[(size_t)(q0 + row) * HD_ + c]);
        }
        asm volatile("cp.async.commit_group;" ::: "memory");
        asm volatile("cp.async.wait_group 0;" ::: "memory");
        __syncthreads();

        // Q fragments -> registers via ldmatrix
        uint32_t qf[4][8];
#pragma unroll
        for (int ck = 0; ck < 4; ck++)
#pragma unroll
            for (int i = 0; i < 2; i++)
                ldsm4(lm_addr(sQ, lane, wm * 32 + i * 16, ck * 16, SH_),
                      qf[ck][i * 4 + 0], qf[ck][i * 4 + 1],
                      qf[ck][i * 4 + 2], qf[ck][i * 4 + 3]);
        __syncthreads();  // Q region now free (E32 aliases it)

        const int nkt = 2 * qt + 2;

        // ================= sweep 1: rowsums =================
        stageK(0, 0);
        asm volatile("cp.async.commit_group;" ::: "memory");

        float rs[2][2] = {{0.f, 0.f}, {0.f, 0.f}};
        for (int kt = 0; kt < nkt; kt++) {
            const int b = kt & 1;
            __syncthreads();
            if (kt + 1 < nkt) {
                stageK(1 - b, (kt + 1) * 64);
                asm volatile("cp.async.commit_group;" ::: "memory");
                asm volatile("cp.async.wait_group 1;" ::: "memory");
            } else {
                asm volatile("cp.async.wait_group 0;" ::: "memory");
            }
            __syncthreads();

            const uint32_t kB = sK + (uint32_t)(b * 64 * SH_) * 2u;
            float s[2][4][4];
#pragma unroll
            for (int i = 0; i < 2; i++)
#pragma unroll
                for (int j = 0; j < 4; j++)
#pragma unroll
                    for (int q = 0; q < 4; q++) s[i][j][q] = 0.f;
#pragma unroll
            for (int ck = 0; ck < 4; ck++) {
                uint32_t bf[4][2];
#pragma unroll
                for (int jp = 0; jp < 2; jp++)
                    ldsm4(lm_addr(kB, lane, wn * 32 + jp * 16, ck * 16, SH_),
                          bf[jp * 2][0], bf[jp * 2 + 1][0],
                          bf[jp * 2][1], bf[jp * 2 + 1][1]);
#pragma unroll
                for (int i = 0; i < 2; i++)
#pragma unroll
                    for (int j = 0; j < 4; j++)
                        mma16(s[i][j], qf[ck][i * 4 + 0], qf[ck][i * 4 + 1],
                              qf[ck][i * 4 + 2], qf[ck][i * 4 + 3], bf[j][0], bf[j][1]);
            }

            const int k0 = kt * 64;
            if (k0 + 63 <= q0 + wm * 32) {
#pragma unroll
                for (int i = 0; i < 2; i++)
#pragma unroll
                    for (int j = 0; j < 4; j++) {
                        rs[i][0] += __expf(s[i][j][0]) + __expf(s[i][j][1]);
                        rs[i][1] += __expf(s[i][j][2]) + __expf(s[i][j][3]);
                    }
            } else {
#pragma unroll
                for (int i = 0; i < 2; i++) {
                    int qiA = q0 + wm * 32 + i * 16 + gg, qiB = qiA + 8;
#pragma unroll
                    for (int j = 0; j < 4; j++) {
                        int ki0 = k0 + wn * 32 + j * 8 + 2 * t4, ki1 = ki0 + 1;
                        rs[i][0] += ((ki0 <= qiA) ? __expf(s[i][j][0]) : 0.f)
                                  + ((ki1 <= qiA) ? __expf(s[i][j][1]) : 0.f);
                        rs[i][1] += ((ki0 <= qiB) ? __expf(s[i][j][2]) : 0.f)
                                  + ((ki1 <= qiB) ? __expf(s[i][j][3]) : 0.f);
                    }
                }
            }
        }
#pragma unroll
        for (int i = 0; i < 2; i++) {
#pragma unroll
            for (int h = 0; h < 2; h++) {
                rs[i][h] += __shfl_xor_sync(0xFFFFFFFF, rs[i][h], 1);
                rs[i][h] += __shfl_xor_sync(0xFFFFFFFF, rs[i][h], 2);
            }
        }
        __syncthreads();
        if (t4 == 0) {
#pragma unroll
            for (int i = 0; i < 2; i++) {
                int r0 = wm * 32 + i * 16 + gg;
                rsc[wn * 128 + r0]     = rs[i][0];
                rsc[wn * 128 + r0 + 8] = rs[i][1];
            }
        }
        __syncthreads();
        if (tid < 128) inv_s[tid] = 1.f / (rsc[tid] + rsc[128 + tid]);
        __syncthreads();

        // ================= sweep 2: P + O =================
        float o[2][4][4];
#pragma unroll
        for (int i = 0; i < 2; i++)
#pragma unroll
            for (int j = 0; j < 4; j++)
#pragma unroll
                for (int q = 0; q < 4; q++) o[i][j][q] = 0.f;

        stageK(0, 0); stageV(0, 0);
        asm volatile("cp.async.commit_group;" ::: "memory");

        for (int kt = 0; kt < S_ / 64; kt++) {
            const int k0 = kt * 64;
            if (kt < nkt) {
                const int b = kt & 1;
                __syncthreads();
                if (kt + 1 < nkt) {
                    stageK(1 - b, (kt + 1) * 64);
                    stageV(1 - b, (kt + 1) * 64);
                    asm volatile("cp.async.commit_group;" ::: "memory");
                    asm volatile("cp.async.wait_group 1;" ::: "memory");
                } else {
                    asm volatile("cp.async.wait_group 0;" ::: "memory");
                }
                __syncthreads();

                const uint32_t kB = sK + (uint32_t)(b * 64 * SH_) * 2u;
                const uint32_t vB = sV + (uint32_t)(b * 64 * SH_) * 2u;

                float s[2][4][4];
#pragma unroll
                for (int i = 0; i < 2; i++)
#pragma unroll
                    for (int j = 0; j < 4; j++)
#pragma unroll
                        for (int q = 0; q < 4; q++) s[i][j][q] = 0.f;
#pragma unroll
                for (int ck = 0; ck < 4; ck++) {
                    uint32_t bf[4][2];
#pragma unroll
                    for (int jp = 0; jp < 2; jp++)
                        ldsm4(lm_addr(kB, lane, wn * 32 + jp * 16, ck * 16, SH_),
                              bf[jp * 2][0], bf[jp * 2 + 1][0],
                              bf[jp * 2][1], bf[jp * 2 + 1][1]);
#pragma unroll
                    for (int i = 0; i < 2; i++)
#pragma unroll
                        for (int j = 0; j < 4; j++)
                            mma16(s[i][j], qf[ck][i * 4 + 0], qf[ck][i * 4 + 1],
                                  qf[ck][i * 4 + 2], qf[ck][i * 4 + 3],
                                  bf[j][0], bf[j][1]);
                }

#pragma unroll
                for (int i = 0; i < 2; i++) {
                    int r0 = wm * 32 + i * 16 + gg;
                    float invA = inv_s[r0], invB = inv_s[r0 + 8];
                    if (k0 + 63 <= q0 + wm * 32) {
#pragma unroll
                        for (int j = 0; j < 4; j++) {
                            s[i][j][0] = __expf(s[i][j][0]) * invA;
                            s[i][j][1] = __expf(s[i][j][1]) * invA;
                            s[i][j][2] = __expf(s[i][j][2]) * invB;
                            s[i][j][3] = __expf(s[i][j][3]) * invB;
                        }
                    } else {
                        int qiA = q0 + r0, qiB = qiA + 8;
#pragma unroll
                        for (int j = 0; j < 4; j++) {
                            int ki0 = k0 + wn * 32 + j * 8 + 2 * t4, ki1 = ki0 + 1;
                            s[i][j][0] = (ki0 <= qiA) ? __expf(s[i][j][0]) * invA : 0.f;
                            s[i][j][1] = (ki1 <= qiA) ? __expf(s[i][j][1]) * invA : 0.f;
                            s[i][j][2] = (ki0 <= qiB) ? __expf(s[i][j][2]) * invB : 0.f;
                            s[i][j][3] = (ki1 <= qiB) ? __expf(s[i][j][3]) * invB : 0.f;
                        }
                    }
                }

                // dual-store E: fp16 for MMA, fp32 for P write
#pragma unroll
                for (int i = 0; i < 2; i++) {
                    int r0 = wm * 32 + i * 16 + gg;
#pragma unroll
                    for (int j = 0; j < 4; j++) {
                        int cl = wn * 32 + j * 8 + 2 * t4;
                        *(uint32_t*)&Eh[r0 * SH_ + cl]       = f2h2(s[i][j][0], s[i][j][1]);
                        *(uint32_t*)&Eh[(r0 + 8) * SH_ + cl] = f2h2(s[i][j][2], s[i][j][3]);
                        if (writeP) {
                            *(float2*)&E32[r0 * SQ_ + cl] =
                                make_float2(s[i][j][0], s[i][j][1]);
                            *(float2*)&E32[(r0 + 8) * SQ_ + cl] =
                                make_float2(s[i][j][2], s[i][j][3]);
                        }
                    }
                }
                __syncthreads();

                if (writeP) {
                    float* Pd = P + (size_t)bh * S_ * S_ + (size_t)q0 * S_ + k0;
#pragma unroll
                    for (int i = 0; i < 8; i++) {
                        int idx = tid + i * 256;
                        int row = idx >> 4, cc = (idx & 15) * 4;
                        *(float4*)&Pd[(size_t)row * S_ + cc] =
                            *(const float4*)&E32[row * SQ_ + cc];
                    }
                }

                // O += E_norm @ V   (ldmatrix frags)
#pragma unroll
                for (int ck = 0; ck < 4; ck++) {
                    uint32_t af[2][4], bf[4][2];
#pragma unroll
                    for (int i = 0; i < 2; i++)
                        ldsm4(lm_addr(sE, lane, wm * 32 + i * 16, ck * 16, SH_),
                              af[i][0], af[i][1], af[i][2], af[i][3]);
#pragma unroll
                    for (int jp = 0; jp < 2; jp++)
                        ldsm4(lm_addr(vB, lane, wn * 32 + jp * 16, ck * 16, SH_),
                              bf[jp * 2][0], bf[jp * 2 + 1][0],
                              bf[jp * 2][1], bf[jp * 2 + 1][1]);
#pragma unroll
                    for (int i = 0; i < 2; i++)
#pragma unroll
                        for (int j = 0; j < 4; j++)
                            mma16(o[i][j], af[i][0], af[i][1], af[i][2], af[i][3],
                                  bf[j][0], bf[j][1]);
                }
            } else if (writeP) {
                float* Pd = P + (size_t)bh * S_ * S_ + (size_t)q0 * S_ + k0;
                const float4 z = make_float4(0.f, 0.f, 0.f, 0.f);
#pragma unroll
                for (int i = 0; i < 8; i++) {
                    int idx = tid + i * 256;
                    int row = idx >> 4, cc = (idx & 15) * 4;
                    *(float4*)&Pd[(size_t)row * S_ + cc] = z;
                }
            }
        }

        // epilogue: O -> g_ao (fp16)
        const int bb = bh >> 4, hh = bh & 15;
#pragma unroll
        for (int i = 0; i < 2; i++) {
            int r0 = wm * 32 + i * 16 + gg;
            int mA = bb * S_ + q0 + r0;
#pragma unroll
            for (int j = 0; j < 4; j++) {
                int cl = hh * 64 + wn * 32 + j * 8 + 2 * t4;
                *(uint32_t*)&g_ao[(size_t)mA * D_ + cl]       = f2h2(o[i][j][0], o[i][j][1]);
                *(uint32_t*)&g_ao[(size_t)(mA + 8) * D_ + cl] = f2h2(o[i][j][2], o[i][j][3]);
            }
        }
    }
}

// ============================================================
extern "C" void kernel_launch(void* const* d_in, const int* in_sizes, int n_in,
                              void* d_out, int out_size)
{
    const float* query = (const float*)d_in[0];
    const float* key_  = (const float*)d_in[1];
    const float* value = (const float*)d_in[2];
    // d_in[3] = causal mask — handled analytically
    const float* Wq = (const float*)d_in[4];
    const float* bq = (const float*)d_in[5];
    const float* Wk = (const float*)d_in[6];
    const float* bk = (const float*)d_in[7];
    const float* Wv = (const float*)d_in[8];
    const float* bv = (const float*)d_in[9];
    const float* Wo = (const float*)d_in[10];
    const float* bo = (const float*)d_in[11];
    float* out = (float*)d_out;

    const long long outN  = (long long)M_ * D_;
    const long long attnN = (long long)BH_ * S_ * S_;

    int hasOut = 1, hasAttn = 0;
    float* Pdst = nullptr;
    if ((long long)out_size >= outN + attnN) { hasAttn = 1; Pdst = out + outN; }
    else if ((long long)out_size == attnN)   { hasOut = 0; hasAttn = 1; Pdst = out; }

    cudaFuncSetAttribute(attn_kernel,
                         cudaFuncAttributeMaxDynamicSharedMemorySize, ATTN_SMEM);
    cudaFuncSetAttribute(gemm_tc_kernel,
                         cudaFuncAttributeMaxDynamicSharedMemorySize, GEMM_SMEM);

    convert_kernel<<<512, 256>>>(
        (const float4*)query, (const float4*)key_, (const float4*)value,
        (const float4*)Wq, (const float4*)Wk, (const float4*)Wv,
        (const float4*)Wo, (const float4*)bq);

    gemm_tc_kernel<<<dim3(D_ / 128, M_ / 128, 3), 256, GEMM_SMEM>>>(
        bk, bv, nullptr, nullptr, 99);

    attn_kernel<<<dim3(NQT2_ / 2, BH_), 256, ATTN_SMEM>>>(Pdst, hasAttn);

    if (hasOut)
        gemm_tc_kernel<<<dim3(D_ / 128, M_ / 128, 1), 256, GEMM_SMEM>>>(
            nullptr, nullptr, bo, out, 0);
}